// round 8
// baseline (speedup 1.0000x reference)
#include <cuda_runtime.h>
#include <cstddef>

#define S_IMG  2048
#define S_TXT  512
#define S_TOT  2560
#define DMODEL 1536
#define NH     24
#define DH     64

typedef unsigned long long ull;

// ---------------- packed fp32x2 helpers (sm_103a FFMA2 path) ----------------
__device__ __forceinline__ ull fma2(ull a, ull b, ull c) {
    ull d; asm("fma.rn.f32x2 %0, %1, %2, %3;" : "=l"(d) : "l"(a), "l"(b), "l"(c)); return d;
}
__device__ __forceinline__ ull pack2(float x, float y) {
    ull d; asm("mov.b64 %0, {%1, %2};" : "=l"(d) : "f"(x), "f"(y)); return d;
}
__device__ __forceinline__ float2 unpack2(ull v) {
    float x, y; asm("mov.b64 {%0, %1}, %2;" : "=f"(x), "=f"(y) : "l"(v));
    return make_float2(x, y);
}

// ---------------- scratch (no allocations allowed) ----------------
__device__ float g_Q[NH * S_TOT * DH];   // [h][s][d]
__device__ float g_K[NH * S_TOT * DH];
__device__ float g_V[NH * S_TOT * DH];
__device__ float g_O[S_TOT * DMODEL];    // [s][h*64+d]

// ================= GEMM core (FMA-bound, FFMA2) =================
struct GemmOut {
    ull acc2[8][4];
};

__device__ __forceinline__ void gemm_core(const float* __restrict__ A,
                                          const float* __restrict__ W,
                                          float* As2 /*[8][264]*/, float* Bs /*[8][132]*/,
                                          GemmOut& G)
{
    const int tid  = threadIdx.x;
    const int trow = tid >> 4;
    const int tcol = tid & 15;
    const int arow = tid >> 1;
    const int acol = (tid & 1) << 2;

    const float* Ap = A + (size_t)arow * DMODEL + acol;
    const float* Wp = W + (size_t)arow * DMODEL + acol;

    #pragma unroll
    for (int i = 0; i < 8; i++)
        #pragma unroll
        for (int j = 0; j < 4; j++) G.acc2[i][j] = 0ull;

    float4 av = *(const float4*)(Ap);
    float4 wv = *(const float4*)(Wp);

    for (int k0 = 0; k0 < DMODEL; k0 += 8) {
        *(ull*)&As2[(acol + 0) * 264 + arow * 2] = pack2(av.x, av.x);
        *(ull*)&As2[(acol + 1) * 264 + arow * 2] = pack2(av.y, av.y);
        *(ull*)&As2[(acol + 2) * 264 + arow * 2] = pack2(av.z, av.z);
        *(ull*)&As2[(acol + 3) * 264 + arow * 2] = pack2(av.w, av.w);
        Bs[(acol + 0) * 132 + arow] = wv.x;
        Bs[(acol + 1) * 132 + arow] = wv.y;
        Bs[(acol + 2) * 132 + arow] = wv.z;
        Bs[(acol + 3) * 132 + arow] = wv.w;
        __syncthreads();

        if (k0 + 8 < DMODEL) {
            av = *(const float4*)(Ap + k0 + 8);
            wv = *(const float4*)(Wp + k0 + 8);
        }

        #pragma unroll
        for (int kk = 0; kk < 8; kk++) {
            ulonglong2 a01 = *(const ulonglong2*)&As2[kk * 264 + trow * 16];
            ulonglong2 a23 = *(const ulonglong2*)&As2[kk * 264 + trow * 16 + 4];
            ulonglong2 a45 = *(const ulonglong2*)&As2[kk * 264 + trow * 16 + 8];
            ulonglong2 a67 = *(const ulonglong2*)&As2[kk * 264 + trow * 16 + 12];
            ulonglong2 b03 = *(const ulonglong2*)&Bs[kk * 132 + tcol * 8];
            ulonglong2 b47 = *(const ulonglong2*)&Bs[kk * 132 + tcol * 8 + 4];
            ull ad[8] = {a01.x, a01.y, a23.x, a23.y, a45.x, a45.y, a67.x, a67.y};
            ull bp[4] = {b03.x, b03.y, b47.x, b47.y};
            #pragma unroll
            for (int i = 0; i < 8; i++)
                #pragma unroll
                for (int j = 0; j < 4; j++)
                    G.acc2[i][j] = fma2(ad[i], bp[j], G.acc2[i][j]);
        }
        __syncthreads();
    }
}

// ---------------- fused QKV projection ----------------
__global__ __launch_bounds__(256, 2)
void gemm_qkv(const float* __restrict__ hid, const float* __restrict__ enc,
              const float* __restrict__ Wq,  const float* __restrict__ Wk,  const float* __restrict__ Wv,
              const float* __restrict__ Waq, const float* __restrict__ Wak, const float* __restrict__ Wav,
              const float* __restrict__ bq,  const float* __restrict__ bk,  const float* __restrict__ bv,
              const float* __restrict__ baq, const float* __restrict__ bak, const float* __restrict__ bav,
              float* __restrict__ Qp, float* __restrict__ Kp, float* __restrict__ Vp)
{
    __shared__ float As2[8 * 264];
    __shared__ float Bs [8 * 132];

    const int nt   = blockIdx.x;
    const int mt   = blockIdx.y;
    const int proj = nt / 12;
    const int n0b  = (nt % 12) * 128;
    const bool txt = (mt < 4);

    const float* A;
    if (txt) A = enc + (size_t)(mt * 128) * DMODEL;
    else     A = hid + (size_t)(mt * 128 - S_TXT) * DMODEL;

    const float* W    = txt ? (proj == 0 ? Waq : proj == 1 ? Wak : Wav)
                            : (proj == 0 ? Wq  : proj == 1 ? Wk  : Wv);
    const float* bias = txt ? (proj == 0 ? baq : proj == 1 ? bak : bav)
                            : (proj == 0 ? bq  : proj == 1 ? bk  : bv);
    float* out = proj == 0 ? Qp : proj == 1 ? Kp : Vp;

    GemmOut G;
    gemm_core(A, W + (size_t)n0b * DMODEL, As2, Bs, G);

    const int trow = threadIdx.x >> 4;
    const int tcol = threadIdx.x & 15;
    const int n0   = n0b + tcol * 8;
    const int h    = n0 >> 6, d0 = n0 & 63;
    float bvv[8];
    #pragma unroll
    for (int j = 0; j < 8; j++) bvv[j] = bias[n0 + j];

    #pragma unroll
    for (int i = 0; i < 8; i++) {
        const int s = mt * 128 + trow * 8 + i;
        float* p = out + (((size_t)h * S_TOT + s) << 6) + d0;
        float2 c0 = unpack2(G.acc2[i][0]), c1 = unpack2(G.acc2[i][1]);
        float2 c2 = unpack2(G.acc2[i][2]), c3 = unpack2(G.acc2[i][3]);
        *(float4*)p       = make_float4(c0.x + bvv[0], c0.y + bvv[1], c1.x + bvv[2], c1.y + bvv[3]);
        *(float4*)(p + 4) = make_float4(c2.x + bvv[4], c2.y + bvv[5], c3.x + bvv[6], c3.y + bvv[7]);
    }
}

// ---------------- fused output projection ----------------
__global__ __launch_bounds__(256, 2)
void gemm_out(const float* __restrict__ Op,
              const float* __restrict__ Wo, const float* __restrict__ Wao,
              const float* __restrict__ bo, const float* __restrict__ bao,
              float* __restrict__ out)
{
    __shared__ float As2[8 * 264];
    __shared__ float Bs [8 * 132];

    const int nt = blockIdx.x;
    const int mt = blockIdx.y;
    const int r0 = mt * 128;
    const bool img = (r0 < S_IMG);

    const float* A    = img ? Op + (size_t)(S_TXT + r0) * DMODEL
                            : Op + (size_t)(r0 - S_IMG) * DMODEL;
    const float* W    = img ? Wo : Wao;
    const float* bias = img ? bo : bao;

    GemmOut G;
    gemm_core(A, W + (size_t)(nt * 128) * DMODEL, As2, Bs, G);

    const int trow = threadIdx.x >> 4;
    const int tcol = threadIdx.x & 15;
    const int n0   = nt * 128 + tcol * 8;
    float bvv[8];
    #pragma unroll
    for (int j = 0; j < 8; j++) bvv[j] = bias[n0 + j];

    #pragma unroll
    for (int i = 0; i < 8; i++) {
        float* p = out + (size_t)(r0 + trow * 8 + i) * DMODEL + n0;
        float2 c0 = unpack2(G.acc2[i][0]), c1 = unpack2(G.acc2[i][1]);
        float2 c2 = unpack2(G.acc2[i][2]), c3 = unpack2(G.acc2[i][3]);
        *(float4*)p       = make_float4(c0.x + bvv[0], c0.y + bvv[1], c1.x + bvv[2], c1.y + bvv[3]);
        *(float4*)(p + 4) = make_float4(c2.x + bvv[4], c2.y + bvv[5], c3.x + bvv[6], c3.y + bvv[7]);
    }
}

// ---------------- RMS-norm + gain + RoPE ----------------
__global__ __launch_bounds__(128)
void rmsrope(float* __restrict__ buf, const float* __restrict__ g_txt,
             const float* __restrict__ g_img, const float* __restrict__ rcos,
             const float* __restrict__ rsin)
{
    const int warp = threadIdx.x >> 5;
    const int lane = threadIdx.x & 31;
    const int row  = blockIdx.x * 4 + warp;
    const int s    = row % S_TOT;

    float2 x = *(float2*)&buf[(size_t)row * 64 + lane * 2];
    float ss = x.x * x.x + x.y * x.y;
    #pragma unroll
    for (int off = 16; off > 0; off >>= 1)
        ss += __shfl_xor_sync(0xffffffffu, ss, off);
    const float r = rsqrtf(ss * (1.0f / 64.0f) + 1e-6f);

    const float* g = (s < S_TXT) ? g_txt : g_img;
    const float y0 = x.x * r * g[lane * 2];
    const float y1 = x.y * r * g[lane * 2 + 1];
    const float c  = rcos[s * 64 + lane * 2];
    const float sn = rsin[s * 64 + lane * 2];
    *(float2*)&buf[(size_t)row * 64 + lane * 2] =
        make_float2(y0 * c - y1 * sn, y1 * c + y0 * sn);
}

// ---------------- fp32 flash attention (FFMA2, smem-balanced) ----------------
// grid (S_TOT/64, NH), 256 threads (16x16), 4x4 micro-tiles.
// Qd: [d][2r] transposed + duplicated (q,q), stride 132  (33 KB)
// Kt: [d][r]  transposed, stride 66                      (16.5 KB)
// Vs: [k][64] natural                                     (16 KB)
// Ps2:[r][2k] duplicated (p,p), stride 132                (33 KB)
// Scores are bounded (|q|=|k|=8 after RMS norm, scale 0.125 -> |s|<=8):
// softmax needs NO running max and NO per-tile rescale.
#define FLASH_SMEM ((64 * 132 + 64 * 66 + 64 * 64 + 64 * 132) * 4)

__global__ __launch_bounds__(256, 2)
void flash(const float* __restrict__ Qb, const float* __restrict__ Kb,
           const float* __restrict__ Vb, float* __restrict__ O)
{
    extern __shared__ float sm[];
    float* Qd  = sm;                   // [64][132]
    float* Kt  = Qd + 64 * 132;        // [64][66]
    float* Vs  = Kt + 64 * 66;         // [64][64]
    float* Ps2 = Vs + 64 * 64;         // [64][132]

    const int tid = threadIdx.x;
    const int ty  = tid >> 4;
    const int tx  = tid & 15;
    const int h   = blockIdx.y;
    const int q0  = blockIdx.x * 64;

    const float* Qg = Qb + (((size_t)h * S_TOT + q0) << 6);
    const float* Kg = Kb + (((size_t)h * S_TOT) << 6);
    const float* Vg = Vb + (((size_t)h * S_TOT) << 6);

    // Stage Q transposed + duplicated, pre-scaled by DH^-0.5 (one-time)
    #pragma unroll
    for (int t = tid; t < 1024; t += 256) {
        const int r = t >> 4, c = (t & 15) << 2;
        float4 v = *(const float4*)(Qg + r * 64 + c);
        float q[4] = {v.x * 0.125f, v.y * 0.125f, v.z * 0.125f, v.w * 0.125f};
        #pragma unroll
        for (int i = 0; i < 4; i++) {
            Qd[(c + i) * 132 + 2 * r]     = q[i];
            Qd[(c + i) * 132 + 2 * r + 1] = q[i];
        }
    }

    float l[4] = {0.f, 0.f, 0.f, 0.f};
    ull o2[4][2];
    #pragma unroll
    for (int i = 0; i < 4; i++) { o2[i][0] = 0ull; o2[i][1] = 0ull; }

    for (int kt = 0; kt < S_TOT / 64; kt++) {
        __syncthreads();   // previous tile's PV done before K/V overwrite
        #pragma unroll
        for (int t = tid; t < 1024; t += 256) {
            const int r = t >> 4, c = (t & 15) << 2;
            float4 kv = *(const float4*)(Kg + (kt * 64 + r) * 64 + c);
            Kt[(c + 0) * 66 + r] = kv.x;
            Kt[(c + 1) * 66 + r] = kv.y;
            Kt[(c + 2) * 66 + r] = kv.z;
            Kt[(c + 3) * 66 + r] = kv.w;
            *(float4*)&Vs[r * 64 + c] = *(const float4*)(Vg + (kt * 64 + r) * 64 + c);
        }
        __syncthreads();

        // S = Q K^T : q dup-pairs straight from Qd, k j-pairs straight from Kt
        ull s2[4][2];
        #pragma unroll
        for (int i = 0; i < 4; i++) { s2[i][0] = 0ull; s2[i][1] = 0ull; }

        #pragma unroll 8
        for (int d = 0; d < 64; d++) {
            const ulonglong2 qa = *(const ulonglong2*)&Qd[d * 132 + 8 * ty];      // (q0,q0),(q1,q1)
            const ulonglong2 qb = *(const ulonglong2*)&Qd[d * 132 + 8 * ty + 4];  // (q2,q2),(q3,q3)
            const ull k01 = *(const ull*)&Kt[d * 66 + 4 * tx];
            const ull k23 = *(const ull*)&Kt[d * 66 + 4 * tx + 2];
            s2[0][0] = fma2(qa.x, k01, s2[0][0]); s2[0][1] = fma2(qa.x, k23, s2[0][1]);
            s2[1][0] = fma2(qa.y, k01, s2[1][0]); s2[1][1] = fma2(qa.y, k23, s2[1][1]);
            s2[2][0] = fma2(qb.x, k01, s2[2][0]); s2[2][1] = fma2(qb.x, k23, s2[2][1]);
            s2[3][0] = fma2(qb.y, k01, s2[3][0]); s2[3][1] = fma2(qb.y, k23, s2[3][1]);
        }

        // exp (no max needed: |s| <= 8), accumulate l, store P duplicated
        #pragma unroll
        for (int i = 0; i < 4; i++) {
            float2 u0 = unpack2(s2[i][0]), u1 = unpack2(s2[i][1]);
            const float p0 = __expf(u0.x), p1 = __expf(u0.y);
            const float p2 = __expf(u1.x), p3 = __expf(u1.y);
            l[i] += (p0 + p1) + (p2 + p3);
            *(float4*)&Ps2[(4 * ty + i) * 132 + 8 * tx]     = make_float4(p0, p0, p1, p1);
            *(float4*)&Ps2[(4 * ty + i) * 132 + 8 * tx + 4] = make_float4(p2, p2, p3, p3);
        }
        __syncwarp();   // each P row is produced & consumed within one warp

        // O += P V : p dup-pairs from Ps2 (broadcast), v j-pairs from Vs
        #pragma unroll 4
        for (int c2 = 0; c2 < 32; c2++) {
            const ulonglong2 vv0 = *(const ulonglong2*)&Vs[(2 * c2) * 64 + 4 * tx];
            const ulonglong2 vv1 = *(const ulonglong2*)&Vs[(2 * c2 + 1) * 64 + 4 * tx];
            #pragma unroll
            for (int i = 0; i < 4; i++) {
                const ulonglong2 pp = *(const ulonglong2*)&Ps2[(4 * ty + i) * 132 + 4 * c2];
                o2[i][0] = fma2(pp.x, vv0.x, o2[i][0]);
                o2[i][1] = fma2(pp.x, vv0.y, o2[i][1]);
                o2[i][0] = fma2(pp.y, vv1.x, o2[i][0]);
                o2[i][1] = fma2(pp.y, vv1.y, o2[i][1]);
            }
        }
    }

    // final l reduction over the 16 tx lanes, then write O[s][h*64+d]
    float* Og = O + (size_t)q0 * DMODEL + h * 64;
    #pragma unroll
    for (int i = 0; i < 4; i++) {
        float rs = l[i];
        #pragma unroll
        for (int off = 8; off > 0; off >>= 1)
            rs += __shfl_xor_sync(0xffffffffu, rs, off);
        const float inv = 1.0f / rs;
        float2 a = unpack2(o2[i][0]), b = unpack2(o2[i][1]);
        *(float4*)(Og + (size_t)(4 * ty + i) * DMODEL + 4 * tx) =
            make_float4(a.x * inv, a.y * inv, b.x * inv, b.y * inv);
    }
}

// ---------------- launch ----------------
extern "C" void kernel_launch(void* const* d_in, const int* in_sizes, int n_in,
                              void* d_out, int out_size)
{
    const float* hid  = (const float*)d_in[0];
    const float* enc  = (const float*)d_in[1];
    const float* rcos = (const float*)d_in[2];
    const float* rsin = (const float*)d_in[3];
    const float* Wq  = (const float*)d_in[4];  const float* bq  = (const float*)d_in[5];
    const float* Wk  = (const float*)d_in[6];  const float* bk  = (const float*)d_in[7];
    const float* Wv  = (const float*)d_in[8];  const float* bv  = (const float*)d_in[9];
    const float* Waq = (const float*)d_in[10]; const float* baq = (const float*)d_in[11];
    const float* Wak = (const float*)d_in[12]; const float* bak = (const float*)d_in[13];
    const float* Wav = (const float*)d_in[14]; const float* bav = (const float*)d_in[15];
    const float* Wo  = (const float*)d_in[16]; const float* bo  = (const float*)d_in[17];
    const float* Wao = (const float*)d_in[18]; const float* bao = (const float*)d_in[19];
    const float* gq  = (const float*)d_in[20]; const float* gk  = (const float*)d_in[21];
    const float* gaq = (const float*)d_in[22]; const float* gak = (const float*)d_in[23];
    float* out = (float*)d_out;

    float *Qp, *Kp, *Vp, *Op;
    cudaGetSymbolAddress((void**)&Qp, g_Q);
    cudaGetSymbolAddress((void**)&Kp, g_K);
    cudaGetSymbolAddress((void**)&Vp, g_V);
    cudaGetSymbolAddress((void**)&Op, g_O);

    // fused QKV projections -> head layout [h][s][d]
    gemm_qkv<<<dim3(36, 20), 256>>>(hid, enc, Wq, Wk, Wv, Waq, Wak, Wav,
                                    bq, bk, bv, baq, bak, bav, Qp, Kp, Vp);

    // RMS norm + gain + RoPE on Q and K
    rmsrope<<<NH * S_TOT / 4, 128>>>(Qp, gaq, gq, rcos, rsin);
    rmsrope<<<NH * S_TOT / 4, 128>>>(Kp, gak, gk, rcos, rsin);

    // flash attention -> O[s][h*64+d]
    cudaFuncSetAttribute(flash, cudaFuncAttributeMaxDynamicSharedMemorySize, FLASH_SMEM);
    flash<<<dim3(S_TOT / 64, NH), 256, FLASH_SMEM>>>(Qp, Kp, Vp, Op);

    // fused output projections
    gemm_out<<<dim3(12, 20), 256>>>(Op, Wo, Wao, bo, bao, out);
}

// round 9
// speedup vs baseline: 1.1357x; 1.1357x over previous
#include <cuda_runtime.h>
#include <cstddef>

#define S_IMG  2048
#define S_TXT  512
#define S_TOT  2560
#define DMODEL 1536
#define NH     24
#define DH     64

typedef unsigned long long ull;

// ---------------- packed fp32x2 helpers (sm_103a FFMA2 path) ----------------
__device__ __forceinline__ ull fma2(ull a, ull b, ull c) {
    ull d; asm("fma.rn.f32x2 %0, %1, %2, %3;" : "=l"(d) : "l"(a), "l"(b), "l"(c)); return d;
}
__device__ __forceinline__ ull pack2(float x, float y) {
    ull d; asm("mov.b64 %0, {%1, %2};" : "=l"(d) : "f"(x), "f"(y)); return d;
}
__device__ __forceinline__ float2 unpack2(ull v) {
    float x, y; asm("mov.b64 {%0, %1}, %2;" : "=f"(x), "=f"(y) : "l"(v));
    return make_float2(x, y);
}

// ---------------- scratch (no allocations allowed) ----------------
__device__ float g_Q[NH * S_TOT * DH];   // [h][s][d]
__device__ float g_K[NH * S_TOT * DH];
__device__ float g_V[NH * S_TOT * DH];
__device__ float g_O[S_TOT * DMODEL];    // [s][h*64+d]

// ================= GEMM core (FMA-bound, FFMA2) — unchanged, known good =================
struct GemmOut {
    ull acc2[8][4];
};

__device__ __forceinline__ void gemm_core(const float* __restrict__ A,
                                          const float* __restrict__ W,
                                          float* As2 /*[8][264]*/, float* Bs /*[8][132]*/,
                                          GemmOut& G)
{
    const int tid  = threadIdx.x;
    const int trow = tid >> 4;
    const int tcol = tid & 15;
    const int arow = tid >> 1;
    const int acol = (tid & 1) << 2;

    const float* Ap = A + (size_t)arow * DMODEL + acol;
    const float* Wp = W + (size_t)arow * DMODEL + acol;

    #pragma unroll
    for (int i = 0; i < 8; i++)
        #pragma unroll
        for (int j = 0; j < 4; j++) G.acc2[i][j] = 0ull;

    float4 av = *(const float4*)(Ap);
    float4 wv = *(const float4*)(Wp);

    for (int k0 = 0; k0 < DMODEL; k0 += 8) {
        *(ull*)&As2[(acol + 0) * 264 + arow * 2] = pack2(av.x, av.x);
        *(ull*)&As2[(acol + 1) * 264 + arow * 2] = pack2(av.y, av.y);
        *(ull*)&As2[(acol + 2) * 264 + arow * 2] = pack2(av.z, av.z);
        *(ull*)&As2[(acol + 3) * 264 + arow * 2] = pack2(av.w, av.w);
        Bs[(acol + 0) * 132 + arow] = wv.x;
        Bs[(acol + 1) * 132 + arow] = wv.y;
        Bs[(acol + 2) * 132 + arow] = wv.z;
        Bs[(acol + 3) * 132 + arow] = wv.w;
        __syncthreads();

        if (k0 + 8 < DMODEL) {
            av = *(const float4*)(Ap + k0 + 8);
            wv = *(const float4*)(Wp + k0 + 8);
        }

        #pragma unroll
        for (int kk = 0; kk < 8; kk++) {
            ulonglong2 a01 = *(const ulonglong2*)&As2[kk * 264 + trow * 16];
            ulonglong2 a23 = *(const ulonglong2*)&As2[kk * 264 + trow * 16 + 4];
            ulonglong2 a45 = *(const ulonglong2*)&As2[kk * 264 + trow * 16 + 8];
            ulonglong2 a67 = *(const ulonglong2*)&As2[kk * 264 + trow * 16 + 12];
            ulonglong2 b03 = *(const ulonglong2*)&Bs[kk * 132 + tcol * 8];
            ulonglong2 b47 = *(const ulonglong2*)&Bs[kk * 132 + tcol * 8 + 4];
            ull ad[8] = {a01.x, a01.y, a23.x, a23.y, a45.x, a45.y, a67.x, a67.y};
            ull bp[4] = {b03.x, b03.y, b47.x, b47.y};
            #pragma unroll
            for (int i = 0; i < 8; i++)
                #pragma unroll
                for (int j = 0; j < 4; j++)
                    G.acc2[i][j] = fma2(ad[i], bp[j], G.acc2[i][j]);
        }
        __syncthreads();
    }
}

// ---------------- fused QKV projection ----------------
__global__ __launch_bounds__(256, 2)
void gemm_qkv(const float* __restrict__ hid, const float* __restrict__ enc,
              const float* __restrict__ Wq,  const float* __restrict__ Wk,  const float* __restrict__ Wv,
              const float* __restrict__ Waq, const float* __restrict__ Wak, const float* __restrict__ Wav,
              const float* __restrict__ bq,  const float* __restrict__ bk,  const float* __restrict__ bv,
              const float* __restrict__ baq, const float* __restrict__ bak, const float* __restrict__ bav,
              float* __restrict__ Qp, float* __restrict__ Kp, float* __restrict__ Vp)
{
    __shared__ float As2[8 * 264];
    __shared__ float Bs [8 * 132];

    const int nt   = blockIdx.x;
    const int mt   = blockIdx.y;
    const int proj = nt / 12;
    const int n0b  = (nt % 12) * 128;
    const bool txt = (mt < 4);

    const float* A;
    if (txt) A = enc + (size_t)(mt * 128) * DMODEL;
    else     A = hid + (size_t)(mt * 128 - S_TXT) * DMODEL;

    const float* W    = txt ? (proj == 0 ? Waq : proj == 1 ? Wak : Wav)
                            : (proj == 0 ? Wq  : proj == 1 ? Wk  : Wv);
    const float* bias = txt ? (proj == 0 ? baq : proj == 1 ? bak : bav)
                            : (proj == 0 ? bq  : proj == 1 ? bk  : bv);
    float* out = proj == 0 ? Qp : proj == 1 ? Kp : Vp;

    GemmOut G;
    gemm_core(A, W + (size_t)n0b * DMODEL, As2, Bs, G);

    const int trow = threadIdx.x >> 4;
    const int tcol = threadIdx.x & 15;
    const int n0   = n0b + tcol * 8;
    const int h    = n0 >> 6, d0 = n0 & 63;
    float bvv[8];
    #pragma unroll
    for (int j = 0; j < 8; j++) bvv[j] = bias[n0 + j];

    #pragma unroll
    for (int i = 0; i < 8; i++) {
        const int s = mt * 128 + trow * 8 + i;
        float* p = out + (((size_t)h * S_TOT + s) << 6) + d0;
        float2 c0 = unpack2(G.acc2[i][0]), c1 = unpack2(G.acc2[i][1]);
        float2 c2 = unpack2(G.acc2[i][2]), c3 = unpack2(G.acc2[i][3]);
        *(float4*)p       = make_float4(c0.x + bvv[0], c0.y + bvv[1], c1.x + bvv[2], c1.y + bvv[3]);
        *(float4*)(p + 4) = make_float4(c2.x + bvv[4], c2.y + bvv[5], c3.x + bvv[6], c3.y + bvv[7]);
    }
}

// ---------------- fused output projection ----------------
__global__ __launch_bounds__(256, 2)
void gemm_out(const float* __restrict__ Op,
              const float* __restrict__ Wo, const float* __restrict__ Wao,
              const float* __restrict__ bo, const float* __restrict__ bao,
              float* __restrict__ out)
{
    __shared__ float As2[8 * 264];
    __shared__ float Bs [8 * 132];

    const int nt = blockIdx.x;
    const int mt = blockIdx.y;
    const int r0 = mt * 128;
    const bool img = (r0 < S_IMG);

    const float* A    = img ? Op + (size_t)(S_TXT + r0) * DMODEL
                            : Op + (size_t)(r0 - S_IMG) * DMODEL;
    const float* W    = img ? Wo : Wao;
    const float* bias = img ? bo : bao;

    GemmOut G;
    gemm_core(A, W + (size_t)(nt * 128) * DMODEL, As2, Bs, G);

    const int trow = threadIdx.x >> 4;
    const int tcol = threadIdx.x & 15;
    const int n0   = nt * 128 + tcol * 8;
    float bvv[8];
    #pragma unroll
    for (int j = 0; j < 8; j++) bvv[j] = bias[n0 + j];

    #pragma unroll
    for (int i = 0; i < 8; i++) {
        float* p = out + (size_t)(r0 + trow * 8 + i) * DMODEL + n0;
        float2 c0 = unpack2(G.acc2[i][0]), c1 = unpack2(G.acc2[i][1]);
        float2 c2 = unpack2(G.acc2[i][2]), c3 = unpack2(G.acc2[i][3]);
        *(float4*)p       = make_float4(c0.x + bvv[0], c0.y + bvv[1], c1.x + bvv[2], c1.y + bvv[3]);
        *(float4*)(p + 4) = make_float4(c2.x + bvv[4], c2.y + bvv[5], c3.x + bvv[6], c3.y + bvv[7]);
    }
}

// ---------------- RMS-norm + gain + RoPE ----------------
__global__ __launch_bounds__(128)
void rmsrope(float* __restrict__ buf, const float* __restrict__ g_txt,
             const float* __restrict__ g_img, const float* __restrict__ rcos,
             const float* __restrict__ rsin)
{
    const int warp = threadIdx.x >> 5;
    const int lane = threadIdx.x & 31;
    const int row  = blockIdx.x * 4 + warp;
    const int s    = row % S_TOT;

    float2 x = *(float2*)&buf[(size_t)row * 64 + lane * 2];
    float ss = x.x * x.x + x.y * x.y;
    #pragma unroll
    for (int off = 16; off > 0; off >>= 1)
        ss += __shfl_xor_sync(0xffffffffu, ss, off);
    const float r = rsqrtf(ss * (1.0f / 64.0f) + 1e-6f);

    const float* g = (s < S_TXT) ? g_txt : g_img;
    const float y0 = x.x * r * g[lane * 2];
    const float y1 = x.y * r * g[lane * 2 + 1];
    const float c  = rcos[s * 64 + lane * 2];
    const float sn = rsin[s * 64 + lane * 2];
    *(float2*)&buf[(size_t)row * 64 + lane * 2] =
        make_float2(y0 * c - y1 * sn, y1 * c + y0 * sn);
}

// ---------------- fp32 flash attention (FFMA2) ----------------
// grid (S_TOT/64, NH), 256 threads (16x16), 4x4 micro-tiles, 3 CTAs/SM.
// Qt: [d][r] transposed, stride 68 (16B-aligned float4 reads)  (17408 fl)
// Kt: [d][r] transposed, stride 66 (conflict-free LDS.64 pairs)(4224*... 64*66 fl)
// Vs: [k][64] natural; Ps: [r][64].
// Scores bounded (|q|=|k|=8 after RMS norm, scale 0.125 -> |s|<=8):
// no running max, no rescale.
#define FLASH_SMEM ((64 * 68 + 64 * 66 + 64 * 64 + 64 * 64) * 4)

__global__ __launch_bounds__(256, 3)
void flash(const float* __restrict__ Qb, const float* __restrict__ Kb,
           const float* __restrict__ Vb, float* __restrict__ O)
{
    extern __shared__ float sm[];
    float* Qt = sm;                  // [64][68]
    float* Kt = Qt + 64 * 68;        // [64][66]
    float* Vs = Kt + 64 * 66;        // [64][64]
    float* Ps = Vs + 64 * 64;        // [64][64]

    const int tid = threadIdx.x;
    const int ty  = tid >> 4;
    const int tx  = tid & 15;
    const int h   = blockIdx.y;
    const int q0  = blockIdx.x * 64;

    const float* Qg = Qb + (((size_t)h * S_TOT + q0) << 6);
    const float* Kg = Kb + (((size_t)h * S_TOT) << 6);
    const float* Vg = Vb + (((size_t)h * S_TOT) << 6);

    // Stage Q transposed, pre-scaled by DH^-0.5 (one-time)
    #pragma unroll
    for (int t = tid; t < 1024; t += 256) {
        const int r = t >> 4, c = (t & 15) << 2;
        float4 v = *(const float4*)(Qg + r * 64 + c);
        Qt[(c + 0) * 68 + r] = v.x * 0.125f;
        Qt[(c + 1) * 68 + r] = v.y * 0.125f;
        Qt[(c + 2) * 68 + r] = v.z * 0.125f;
        Qt[(c + 3) * 68 + r] = v.w * 0.125f;
    }

    float l[4] = {0.f, 0.f, 0.f, 0.f};
    ull o2[4][2];
    #pragma unroll
    for (int i = 0; i < 4; i++) { o2[i][0] = 0ull; o2[i][1] = 0ull; }

    for (int kt = 0; kt < S_TOT / 64; kt++) {
        __syncthreads();   // previous tile's PV done before K/V overwrite
        #pragma unroll
        for (int t = tid; t < 1024; t += 256) {
            const int r = t >> 4, c = (t & 15) << 2;
            float4 kv = *(const float4*)(Kg + (kt * 64 + r) * 64 + c);
            Kt[(c + 0) * 66 + r] = kv.x;
            Kt[(c + 1) * 66 + r] = kv.y;
            Kt[(c + 2) * 66 + r] = kv.z;
            Kt[(c + 3) * 66 + r] = kv.w;
            *(float4*)&Vs[r * 64 + c] = *(const float4*)(Vg + (kt * 64 + r) * 64 + c);
        }
        __syncthreads();

        // S = Q K^T : q via one LDS.128 (broadcast), k j-pairs direct from Kt,
        // q dups built on the (idle) ALU pipe.
        ull s2[4][2];   // [i][jp]: (s_j0,s_j1),(s_j2,s_j3) for row 4*ty+i
        #pragma unroll
        for (int i = 0; i < 4; i++) { s2[i][0] = 0ull; s2[i][1] = 0ull; }

        #pragma unroll 8
        for (int d = 0; d < 64; d++) {
            const float4 qv = *(const float4*)&Qt[d * 68 + 4 * ty];
            const ull k01 = *(const ull*)&Kt[d * 66 + 4 * tx];
            const ull k23 = *(const ull*)&Kt[d * 66 + 4 * tx + 2];
            const ull q0d = pack2(qv.x, qv.x), q1d = pack2(qv.y, qv.y);
            const ull q2d = pack2(qv.z, qv.z), q3d = pack2(qv.w, qv.w);
            s2[0][0] = fma2(q0d, k01, s2[0][0]); s2[0][1] = fma2(q0d, k23, s2[0][1]);
            s2[1][0] = fma2(q1d, k01, s2[1][0]); s2[1][1] = fma2(q1d, k23, s2[1][1]);
            s2[2][0] = fma2(q2d, k01, s2[2][0]); s2[2][1] = fma2(q2d, k23, s2[2][1]);
            s2[3][0] = fma2(q3d, k01, s2[3][0]); s2[3][1] = fma2(q3d, k23, s2[3][1]);
        }

        // exp (no max needed: |s| <= 8), accumulate l, store P
        #pragma unroll
        for (int i = 0; i < 4; i++) {
            float2 u0 = unpack2(s2[i][0]), u1 = unpack2(s2[i][1]);
            const float p0 = __expf(u0.x), p1 = __expf(u0.y);
            const float p2 = __expf(u1.x), p3 = __expf(u1.y);
            l[i] += (p0 + p1) + (p2 + p3);
            *(float4*)&Ps[(4 * ty + i) * 64 + 4 * tx] = make_float4(p0, p1, p2, p3);
        }
        __syncwarp();   // each P row is produced & consumed within one warp

        // O += P V : p scalar broadcast + dup on ALU, v j-pairs natural
        #pragma unroll 4
        for (int k = 0; k < 64; k++) {
            const ulonglong2 vv = *(const ulonglong2*)&Vs[k * 64 + 4 * tx];
            #pragma unroll
            for (int i = 0; i < 4; i++) {
                const float pv = Ps[(4 * ty + i) * 64 + k];
                const ull pd = pack2(pv, pv);
                o2[i][0] = fma2(pd, vv.x, o2[i][0]);
                o2[i][1] = fma2(pd, vv.y, o2[i][1]);
            }
        }
    }

    // final l reduction over the 16 tx lanes, then write O[s][h*64+d]
    float* Og = O + (size_t)q0 * DMODEL + h * 64;
    #pragma unroll
    for (int i = 0; i < 4; i++) {
        float rs = l[i];
        #pragma unroll
        for (int off = 8; off > 0; off >>= 1)
            rs += __shfl_xor_sync(0xffffffffu, rs, off);
        const float inv = 1.0f / rs;
        float2 a = unpack2(o2[i][0]), b = unpack2(o2[i][1]);
        *(float4*)(Og + (size_t)(4 * ty + i) * DMODEL + 4 * tx) =
            make_float4(a.x * inv, a.y * inv, b.x * inv, b.y * inv);
    }
}

// ---------------- launch ----------------
extern "C" void kernel_launch(void* const* d_in, const int* in_sizes, int n_in,
                              void* d_out, int out_size)
{
    const float* hid  = (const float*)d_in[0];
    const float* enc  = (const float*)d_in[1];
    const float* rcos = (const float*)d_in[2];
    const float* rsin = (const float*)d_in[3];
    const float* Wq  = (const float*)d_in[4];  const float* bq  = (const float*)d_in[5];
    const float* Wk  = (const float*)d_in[6];  const float* bk  = (const float*)d_in[7];
    const float* Wv  = (const float*)d_in[8];  const float* bv  = (const float*)d_in[9];
    const float* Waq = (const float*)d_in[10]; const float* baq = (const float*)d_in[11];
    const float* Wak = (const float*)d_in[12]; const float* bak = (const float*)d_in[13];
    const float* Wav = (const float*)d_in[14]; const float* bav = (const float*)d_in[15];
    const float* Wo  = (const float*)d_in[16]; const float* bo  = (const float*)d_in[17];
    const float* Wao = (const float*)d_in[18]; const float* bao = (const float*)d_in[19];
    const float* gq  = (const float*)d_in[20]; const float* gk  = (const float*)d_in[21];
    const float* gaq = (const float*)d_in[22]; const float* gak = (const float*)d_in[23];
    float* out = (float*)d_out;

    float *Qp, *Kp, *Vp, *Op;
    cudaGetSymbolAddress((void**)&Qp, g_Q);
    cudaGetSymbolAddress((void**)&Kp, g_K);
    cudaGetSymbolAddress((void**)&Vp, g_V);
    cudaGetSymbolAddress((void**)&Op, g_O);

    // fused QKV projections -> head layout [h][s][d]
    gemm_qkv<<<dim3(36, 20), 256>>>(hid, enc, Wq, Wk, Wv, Waq, Wak, Wav,
                                    bq, bk, bv, baq, bak, bav, Qp, Kp, Vp);

    // RMS norm + gain + RoPE on Q and K
    rmsrope<<<NH * S_TOT / 4, 128>>>(Qp, gaq, gq, rcos, rsin);
    rmsrope<<<NH * S_TOT / 4, 128>>>(Kp, gak, gk, rcos, rsin);

    // flash attention -> O[s][h*64+d]
    cudaFuncSetAttribute(flash, cudaFuncAttributeMaxDynamicSharedMemorySize, FLASH_SMEM);
    flash<<<dim3(S_TOT / 64, NH), 256, FLASH_SMEM>>>(Qp, Kp, Vp, Op);

    // fused output projections
    gemm_out<<<dim3(12, 20), 256>>>(Op, Wo, Wao, bo, bao, out);
}

// round 11
// speedup vs baseline: 1.6441x; 1.4476x over previous
#include <cuda_runtime.h>
#include <cuda_bf16.h>
#include <cstddef>
#include <cstdint>

#define S_IMG  2048
#define S_TXT  512
#define S_TOT  2560
#define DMODEL 1536
#define NH     24
#define DH     64

typedef unsigned long long ull;

// ---------------- packed fp32x2 helpers (flash) ----------------
__device__ __forceinline__ ull fma2(ull a, ull b, ull c) {
    ull d; asm("fma.rn.f32x2 %0, %1, %2, %3;" : "=l"(d) : "l"(a), "l"(b), "l"(c)); return d;
}
__device__ __forceinline__ ull pack2(float x, float y) {
    ull d; asm("mov.b64 %0, {%1, %2};" : "=l"(d) : "f"(x), "f"(y)); return d;
}
__device__ __forceinline__ float2 unpack2(ull v) {
    float x, y; asm("mov.b64 {%0, %1}, %2;" : "=f"(x), "=f"(y) : "l"(v));
    return make_float2(x, y);
}

// ---------------- scratch (no allocations allowed) ----------------
#define WSZ (DMODEL * DMODEL)
__device__ float g_Q[NH * S_TOT * DH];                        // [h][s][d]
__device__ float g_K[NH * S_TOT * DH];
__device__ float g_V[NH * S_TOT * DH];
__device__ float g_O[S_TOT * DMODEL];                         // [s][h*64+d]
__device__ __align__(16) __nv_bfloat16 g_Whi[8 * WSZ];        // Wq,Wk,Wv,Waq,Wak,Wav,Wo,Wao
__device__ __align__(16) __nv_bfloat16 g_Wlo[8 * WSZ];
__device__ __align__(16) __nv_bfloat16 g_Xhi[S_TOT * DMODEL]; // rows 0..511 enc, 512.. hid
__device__ __align__(16) __nv_bfloat16 g_Xlo[S_TOT * DMODEL];
__device__ __align__(16) __nv_bfloat16 g_Ohi[S_TOT * DMODEL];
__device__ __align__(16) __nv_bfloat16 g_Olo[S_TOT * DMODEL];

// ---------------- bf16 split: x = hi + lo ----------------
__global__ void split_bf16(const float* __restrict__ src, __nv_bfloat16* __restrict__ hi,
                           __nv_bfloat16* __restrict__ lo, int n)
{
    int i = blockIdx.x * 256 + threadIdx.x;
    if (i < n) {
        float x = src[i];
        __nv_bfloat16 h = __float2bfloat16(x);
        hi[i] = h;
        lo[i] = __float2bfloat16(x - __bfloat162float(h));
    }
}

// ================= warp-MMA bf16 GEMM (mma.sync m16n8k16, HMMA path) =================
// Y[128m x 128n] = Ah*W^T terms over K=1536; 256 threads, 8 warps (4m x 2n),
// each warp 32x64 = 2(m) x 8(n) mma tiles. 3-term split: AhWh + AhWl + AlWh.
// Smem: double-buffered BK=32 chunks, 4 tensors (Ah,Al,Wh,Wl), stride 40 bf16.
#define GBK      32
#define GSTRIDE  40                       // bf16 per smem row (conflict-free frag LDS)
#define GBUF     (128 * GSTRIDE * 2)      // 10240 B per tensor tile
#define GSTAGE   (4 * GBUF)               // 40960 B per stage
#define GEMM_SMEM (2 * GSTAGE)            // 81920 B

__device__ __forceinline__ unsigned smem_u32(const void* p) {
    unsigned a;
    asm("{ .reg .u64 t; cvta.to.shared.u64 t, %1; cvt.u32.u64 %0, t; }" : "=r"(a) : "l"(p));
    return a;
}
__device__ __forceinline__ void cp16(unsigned dst, const void* src) {
    asm volatile("cp.async.cg.shared.global [%0], [%1], 16;" :: "r"(dst), "l"(src) : "memory");
}
__device__ __forceinline__ uint32_t lds_bf2(const __nv_bfloat16* base, int elem) {
    return *(const uint32_t*)(base + elem);
}
__device__ __forceinline__ void mma16816(float* c, const uint32_t* a, uint32_t b0, uint32_t b1) {
    asm volatile(
        "mma.sync.aligned.m16n8k16.row.col.f32.bf16.bf16.f32 "
        "{%0,%1,%2,%3}, {%4,%5,%6,%7}, {%8,%9}, {%0,%1,%2,%3};"
        : "+f"(c[0]), "+f"(c[1]), "+f"(c[2]), "+f"(c[3])
        : "r"(a[0]), "r"(a[1]), "r"(a[2]), "r"(a[3]), "r"(b0), "r"(b1));
}

// core: fills acc[2][8][4]; A/W are 128-row slices with row stride DMODEL (bf16)
__device__ void mma_core(const __nv_bfloat16* __restrict__ Ah, const __nv_bfloat16* __restrict__ Al,
                         const __nv_bfloat16* __restrict__ Wh, const __nv_bfloat16* __restrict__ Wl,
                         char* smem, float acc[2][8][4])
{
    const int tid  = threadIdx.x;
    const int lane = tid & 31;
    const int wid  = tid >> 5;
    const int Rm   = (wid & 3) * 32;
    const int Cn   = (wid >> 2) * 64;
    const int gp   = lane >> 2;        // group id (row/col within tile)
    const int qd   = lane & 3;         // quad

    const unsigned sb = smem_u32(smem);
    const __nv_bfloat16* gsrc[4] = {Ah, Al, Wh, Wl};

    // issue one chunk's 4 tiles (128 rows x 32 bf16) via cp.async
    auto issue = [&](int c, int stage) {
        #pragma unroll
        for (int t4 = 0; t4 < 4; t4++) {
            const __nv_bfloat16* s = gsrc[t4] + c * GBK;
            const unsigned dbase = sb + stage * GSTAGE + t4 * GBUF;
            #pragma unroll
            for (int i = 0; i < 2; i++) {
                const int idx = tid + i * 256;          // 512 x uint4
                const int row = idx >> 2, cg = idx & 3; // 4 col-groups of 8 bf16
                cp16(dbase + (row * GSTRIDE + cg * 8) * 2,
                     s + (size_t)row * DMODEL + cg * 8);
            }
        }
        asm volatile("cp.async.commit_group;" ::: "memory");
    };

    #pragma unroll
    for (int mi = 0; mi < 2; mi++)
        #pragma unroll
        for (int ni = 0; ni < 8; ni++)
            #pragma unroll
            for (int j = 0; j < 4; j++) acc[mi][ni][j] = 0.0f;

    issue(0, 0);

    for (int c = 0; c < DMODEL / GBK; c++) {
        asm volatile("cp.async.wait_group 0;" ::: "memory");
        __syncthreads();                    // chunk c visible; all warps done with prev stage
        if (c + 1 < DMODEL / GBK) issue(c + 1, (c + 1) & 1);

        const char* st = smem + (c & 1) * GSTAGE;
        const __nv_bfloat16* sAh = (const __nv_bfloat16*)(st);
        const __nv_bfloat16* sAl = (const __nv_bfloat16*)(st + GBUF);
        const __nv_bfloat16* sWh = (const __nv_bfloat16*)(st + 2 * GBUF);
        const __nv_bfloat16* sWl = (const __nv_bfloat16*)(st + 3 * GBUF);

        #pragma unroll
        for (int k0 = 0; k0 < GBK; k0 += 16) {
            uint32_t ah[2][4], al[2][4];
            #pragma unroll
            for (int mi = 0; mi < 2; mi++) {
                const int r = Rm + mi * 16 + gp;
                const int k = k0 + qd * 2;
                ah[mi][0] = lds_bf2(sAh, r * GSTRIDE + k);
                ah[mi][1] = lds_bf2(sAh, (r + 8) * GSTRIDE + k);
                ah[mi][2] = lds_bf2(sAh, r * GSTRIDE + k + 8);
                ah[mi][3] = lds_bf2(sAh, (r + 8) * GSTRIDE + k + 8);
                al[mi][0] = lds_bf2(sAl, r * GSTRIDE + k);
                al[mi][1] = lds_bf2(sAl, (r + 8) * GSTRIDE + k);
                al[mi][2] = lds_bf2(sAl, r * GSTRIDE + k + 8);
                al[mi][3] = lds_bf2(sAl, (r + 8) * GSTRIDE + k + 8);
            }
            #pragma unroll
            for (int ni = 0; ni < 8; ni++) {
                const int n = Cn + ni * 8 + gp;
                const int k = k0 + qd * 2;
                const uint32_t bh0 = lds_bf2(sWh, n * GSTRIDE + k);
                const uint32_t bh1 = lds_bf2(sWh, n * GSTRIDE + k + 8);
                const uint32_t bl0 = lds_bf2(sWl, n * GSTRIDE + k);
                const uint32_t bl1 = lds_bf2(sWl, n * GSTRIDE + k + 8);
                #pragma unroll
                for (int mi = 0; mi < 2; mi++) {
                    mma16816(acc[mi][ni], ah[mi], bh0, bh1);
                    mma16816(acc[mi][ni], ah[mi], bl0, bl1);
                    mma16816(acc[mi][ni], al[mi], bh0, bh1);
                }
            }
        }
    }
}

// ---------------- QKV projection (warp MMA) ----------------
// grid (36, 20): bx -> proj (bx/12) + n-tile (bx%12); mt: rows (txt 0..3, img 4..19)
__global__ __launch_bounds__(256)
void qkv_mma(const __nv_bfloat16* __restrict__ Xhi, const __nv_bfloat16* __restrict__ Xlo,
             const __nv_bfloat16* __restrict__ Whi8, const __nv_bfloat16* __restrict__ Wlo8,
             const float* __restrict__ bq, const float* __restrict__ bk, const float* __restrict__ bv,
             const float* __restrict__ baq, const float* __restrict__ bak, const float* __restrict__ bav,
             float* __restrict__ Qp, float* __restrict__ Kp, float* __restrict__ Vp)
{
    extern __shared__ __align__(16) char smem[];
    const int bx = blockIdx.x, mt = blockIdx.y;
    const int proj = bx / 12;
    const int n0b  = (bx % 12) * 128;
    const bool txt = (mt < 4);
    const int widx = (txt ? 3 : 0) + proj;

    const __nv_bfloat16* Ah = Xhi + (size_t)mt * 128 * DMODEL;
    const __nv_bfloat16* Al = Xlo + (size_t)mt * 128 * DMODEL;
    const __nv_bfloat16* Wh = Whi8 + (size_t)widx * WSZ + (size_t)n0b * DMODEL;
    const __nv_bfloat16* Wl = Wlo8 + (size_t)widx * WSZ + (size_t)n0b * DMODEL;
    const float* bias = txt ? (proj == 0 ? baq : proj == 1 ? bak : bav)
                            : (proj == 0 ? bq  : proj == 1 ? bk  : bv);
    float* out = proj == 0 ? Qp : proj == 1 ? Kp : Vp;

    float acc[2][8][4];
    mma_core(Ah, Al, Wh, Wl, smem, acc);

    const int lane = threadIdx.x & 31, wid = threadIdx.x >> 5;
    const int Rm = (wid & 3) * 32, Cn = (wid >> 2) * 64;
    const int gp = lane >> 2, qd = lane & 3;

    #pragma unroll
    for (int ni = 0; ni < 8; ni++) {
        const int n0 = n0b + Cn + ni * 8;                 // 8-col group, one head
        const int h = n0 >> 6, d0 = (n0 & 63) + qd * 2;
        const float2 bb = *(const float2*)&bias[n0 + qd * 2];
        #pragma unroll
        for (int mi = 0; mi < 2; mi++) {
            const int s = mt * 128 + Rm + mi * 16 + gp;   // txt rows 0..511, img 512..
            float* p0 = out + (((size_t)h * S_TOT + s) << 6) + d0;
            float* p1 = out + (((size_t)h * S_TOT + s + 8) << 6) + d0;
            *(float2*)p0 = make_float2(acc[mi][ni][0] + bb.x, acc[mi][ni][1] + bb.y);
            *(float2*)p1 = make_float2(acc[mi][ni][2] + bb.x, acc[mi][ni][3] + bb.y);
        }
    }
}

// ---------------- output projection (warp MMA) ----------------
// grid (12, 20): d_out rows 0..2047 img (O rows 512..), 2048..2559 enc (O rows 0..511)
__global__ __launch_bounds__(256)
void out_mma(const __nv_bfloat16* __restrict__ Ohi, const __nv_bfloat16* __restrict__ Olo,
             const __nv_bfloat16* __restrict__ Whi8, const __nv_bfloat16* __restrict__ Wlo8,
             const float* __restrict__ bo, const float* __restrict__ bao,
             float* __restrict__ out)
{
    extern __shared__ __align__(16) char smem[];
    const int nt = blockIdx.x, mt = blockIdx.y;
    const int r0 = mt * 128;
    const bool img = (r0 < S_IMG);
    const size_t arow = img ? (size_t)(S_TXT + r0) : (size_t)(r0 - S_IMG);
    const int widx = img ? 6 : 7;

    const __nv_bfloat16* Ah = Ohi + arow * DMODEL;
    const __nv_bfloat16* Al = Olo + arow * DMODEL;
    const __nv_bfloat16* Wh = Whi8 + (size_t)widx * WSZ + (size_t)nt * 128 * DMODEL;
    const __nv_bfloat16* Wl = Wlo8 + (size_t)widx * WSZ + (size_t)nt * 128 * DMODEL;
    const float* bias = img ? bo : bao;

    float acc[2][8][4];
    mma_core(Ah, Al, Wh, Wl, smem, acc);

    const int lane = threadIdx.x & 31, wid = threadIdx.x >> 5;
    const int Rm = (wid & 3) * 32, Cn = (wid >> 2) * 64;
    const int gp = lane >> 2, qd = lane & 3;

    #pragma unroll
    for (int ni = 0; ni < 8; ni++) {
        const int n0 = nt * 128 + Cn + ni * 8 + qd * 2;
        const float2 bb = *(const float2*)&bias[n0];
        #pragma unroll
        for (int mi = 0; mi < 2; mi++) {
            const int m = r0 + Rm + mi * 16 + gp;
            *(float2*)(out + (size_t)m * DMODEL + n0) =
                make_float2(acc[mi][ni][0] + bb.x, acc[mi][ni][1] + bb.y);
            *(float2*)(out + (size_t)(m + 8) * DMODEL + n0) =
                make_float2(acc[mi][ni][2] + bb.x, acc[mi][ni][3] + bb.y);
        }
    }
}

// ---------------- RMS-norm + gain + RoPE (unchanged) ----------------
__global__ __launch_bounds__(128)
void rmsrope(float* __restrict__ buf, const float* __restrict__ g_txt,
             const float* __restrict__ g_img, const float* __restrict__ rcos,
             const float* __restrict__ rsin)
{
    const int warp = threadIdx.x >> 5;
    const int lane = threadIdx.x & 31;
    const int row  = blockIdx.x * 4 + warp;
    const int s    = row % S_TOT;

    float2 x = *(float2*)&buf[(size_t)row * 64 + lane * 2];
    float ss = x.x * x.x + x.y * x.y;
    #pragma unroll
    for (int off = 16; off > 0; off >>= 1)
        ss += __shfl_xor_sync(0xffffffffu, ss, off);
    const float r = rsqrtf(ss * (1.0f / 64.0f) + 1e-6f);

    const float* g = (s < S_TXT) ? g_txt : g_img;
    const float y0 = x.x * r * g[lane * 2];
    const float y1 = x.y * r * g[lane * 2 + 1];
    const float c  = rcos[s * 64 + lane * 2];
    const float sn = rsin[s * 64 + lane * 2];
    *(float2*)&buf[(size_t)row * 64 + lane * 2] =
        make_float2(y0 * c - y1 * sn, y1 * c + y0 * sn);
}

// ---------------- fp32 flash attention (round-9 best, unchanged) ----------------
#define FLASH_SMEM ((64 * 68 + 64 * 66 + 64 * 64 + 64 * 64) * 4)

__global__ __launch_bounds__(256, 3)
void flash(const float* __restrict__ Qb, const float* __restrict__ Kb,
           const float* __restrict__ Vb, float* __restrict__ O)
{
    extern __shared__ float sm[];
    float* Qt = sm;                  // [64][68]
    float* Kt = Qt + 64 * 68;        // [64][66]
    float* Vs = Kt + 64 * 66;        // [64][64]
    float* Ps = Vs + 64 * 64;        // [64][64]

    const int tid = threadIdx.x;
    const int ty  = tid >> 4;
    const int tx  = tid & 15;
    const int h   = blockIdx.y;
    const int q0  = blockIdx.x * 64;

    const float* Qg = Qb + (((size_t)h * S_TOT + q0) << 6);
    const float* Kg = Kb + (((size_t)h * S_TOT) << 6);
    const float* Vg = Vb + (((size_t)h * S_TOT) << 6);

    #pragma unroll
    for (int t = tid; t < 1024; t += 256) {
        const int r = t >> 4, c = (t & 15) << 2;
        float4 v = *(const float4*)(Qg + r * 64 + c);
        Qt[(c + 0) * 68 + r] = v.x * 0.125f;
        Qt[(c + 1) * 68 + r] = v.y * 0.125f;
        Qt[(c + 2) * 68 + r] = v.z * 0.125f;
        Qt[(c + 3) * 68 + r] = v.w * 0.125f;
    }

    float l[4] = {0.f, 0.f, 0.f, 0.f};
    ull o2[4][2];
    #pragma unroll
    for (int i = 0; i < 4; i++) { o2[i][0] = 0ull; o2[i][1] = 0ull; }

    for (int kt = 0; kt < S_TOT / 64; kt++) {
        __syncthreads();
        #pragma unroll
        for (int t = tid; t < 1024; t += 256) {
            const int r = t >> 4, c = (t & 15) << 2;
            float4 kv = *(const float4*)(Kg + (kt * 64 + r) * 64 + c);
            Kt[(c + 0) * 66 + r] = kv.x;
            Kt[(c + 1) * 66 + r] = kv.y;
            Kt[(c + 2) * 66 + r] = kv.z;
            Kt[(c + 3) * 66 + r] = kv.w;
            *(float4*)&Vs[r * 64 + c] = *(const float4*)(Vg + (kt * 64 + r) * 64 + c);
        }
        __syncthreads();

        ull s2[4][2];
        #pragma unroll
        for (int i = 0; i < 4; i++) { s2[i][0] = 0ull; s2[i][1] = 0ull; }

        #pragma unroll 8
        for (int d = 0; d < 64; d++) {
            const float4 qv = *(const float4*)&Qt[d * 68 + 4 * ty];
            const ull k01 = *(const ull*)&Kt[d * 66 + 4 * tx];
            const ull k23 = *(const ull*)&Kt[d * 66 + 4 * tx + 2];
            const ull q0d = pack2(qv.x, qv.x), q1d = pack2(qv.y, qv.y);
            const ull q2d = pack2(qv.z, qv.z), q3d = pack2(qv.w, qv.w);
            s2[0][0] = fma2(q0d, k01, s2[0][0]); s2[0][1] = fma2(q0d, k23, s2[0][1]);
            s2[1][0] = fma2(q1d, k01, s2[1][0]); s2[1][1] = fma2(q1d, k23, s2[1][1]);
            s2[2][0] = fma2(q2d, k01, s2[2][0]); s2[2][1] = fma2(q2d, k23, s2[2][1]);
            s2[3][0] = fma2(q3d, k01, s2[3][0]); s2[3][1] = fma2(q3d, k23, s2[3][1]);
        }

        #pragma unroll
        for (int i = 0; i < 4; i++) {
            float2 u0 = unpack2(s2[i][0]), u1 = unpack2(s2[i][1]);
            const float p0 = __expf(u0.x), p1 = __expf(u0.y);
            const float p2 = __expf(u1.x), p3 = __expf(u1.y);
            l[i] += (p0 + p1) + (p2 + p3);
            *(float4*)&Ps[(4 * ty + i) * 64 + 4 * tx] = make_float4(p0, p1, p2, p3);
        }
        __syncwarp();

        #pragma unroll 4
        for (int k = 0; k < 64; k++) {
            const ulonglong2 vv = *(const ulonglong2*)&Vs[k * 64 + 4 * tx];
            #pragma unroll
            for (int i = 0; i < 4; i++) {
                const float pv = Ps[(4 * ty + i) * 64 + k];
                const ull pd = pack2(pv, pv);
                o2[i][0] = fma2(pd, vv.x, o2[i][0]);
                o2[i][1] = fma2(pd, vv.y, o2[i][1]);
            }
        }
    }

    float* Og = O + (size_t)q0 * DMODEL + h * 64;
    #pragma unroll
    for (int i = 0; i < 4; i++) {
        float rs = l[i];
        #pragma unroll
        for (int off = 8; off > 0; off >>= 1)
            rs += __shfl_xor_sync(0xffffffffu, rs, off);
        const float inv = 1.0f / rs;
        float2 a = unpack2(o2[i][0]), b = unpack2(o2[i][1]);
        *(float4*)(Og + (size_t)(4 * ty + i) * DMODEL + 4 * tx) =
            make_float4(a.x * inv, a.y * inv, b.x * inv, b.y * inv);
    }
}

// ---------------- launch ----------------
extern "C" void kernel_launch(void* const* d_in, const int* in_sizes, int n_in,
                              void* d_out, int out_size)
{
    const float* hid  = (const float*)d_in[0];
    const float* enc  = (const float*)d_in[1];
    const float* rcos = (const float*)d_in[2];
    const float* rsin = (const float*)d_in[3];
    const float* Wq  = (const float*)d_in[4];  const float* bq  = (const float*)d_in[5];
    const float* Wk  = (const float*)d_in[6];  const float* bk  = (const float*)d_in[7];
    const float* Wv  = (const float*)d_in[8];  const float* bv  = (const float*)d_in[9];
    const float* Waq = (const float*)d_in[10]; const float* baq = (const float*)d_in[11];
    const float* Wak = (const float*)d_in[12]; const float* bak = (const float*)d_in[13];
    const float* Wav = (const float*)d_in[14]; const float* bav = (const float*)d_in[15];
    const float* Wo  = (const float*)d_in[16]; const float* bo  = (const float*)d_in[17];
    const float* Wao = (const float*)d_in[18]; const float* bao = (const float*)d_in[19];
    const float* gq  = (const float*)d_in[20]; const float* gk  = (const float*)d_in[21];
    const float* gaq = (const float*)d_in[22]; const float* gak = (const float*)d_in[23];
    float* out = (float*)d_out;

    float *Qp, *Kp, *Vp, *Op;
    cudaGetSymbolAddress((void**)&Qp, g_Q);
    cudaGetSymbolAddress((void**)&Kp, g_K);
    cudaGetSymbolAddress((void**)&Vp, g_V);
    cudaGetSymbolAddress((void**)&Op, g_O);
    __nv_bfloat16 *WhiP, *WloP, *XhiP, *XloP, *OhiP, *OloP;
    cudaGetSymbolAddress((void**)&WhiP, g_Whi);
    cudaGetSymbolAddress((void**)&WloP, g_Wlo);
    cudaGetSymbolAddress((void**)&XhiP, g_Xhi);
    cudaGetSymbolAddress((void**)&XloP, g_Xlo);
    cudaGetSymbolAddress((void**)&OhiP, g_Ohi);
    cudaGetSymbolAddress((void**)&OloP, g_Olo);

    // bf16 splits of weights and activations
    const float* Ws[8] = {Wq, Wk, Wv, Waq, Wak, Wav, Wo, Wao};
    const int wb = (WSZ + 255) / 256;
    for (int i = 0; i < 8; i++)
        split_bf16<<<wb, 256>>>(Ws[i], WhiP + (size_t)i * WSZ, WloP + (size_t)i * WSZ, WSZ);
    split_bf16<<<(S_TXT * DMODEL + 255) / 256, 256>>>(enc, XhiP, XloP, S_TXT * DMODEL);
    split_bf16<<<(S_IMG * DMODEL + 255) / 256, 256>>>(hid, XhiP + (size_t)S_TXT * DMODEL,
                                                      XloP + (size_t)S_TXT * DMODEL, S_IMG * DMODEL);

    // QKV projections on tensor cores (warp MMA) -> [h][s][d]
    cudaFuncSetAttribute(qkv_mma, cudaFuncAttributeMaxDynamicSharedMemorySize, GEMM_SMEM);
    qkv_mma<<<dim3(36, 20), 256, GEMM_SMEM>>>(XhiP, XloP, WhiP, WloP,
                                              bq, bk, bv, baq, bak, bav, Qp, Kp, Vp);

    // RMS norm + gain + RoPE on Q and K
    rmsrope<<<NH * S_TOT / 4, 128>>>(Qp, gaq, gq, rcos, rsin);
    rmsrope<<<NH * S_TOT / 4, 128>>>(Kp, gak, gk, rcos, rsin);

    // flash attention -> O[s][h*64+d]
    cudaFuncSetAttribute(flash, cudaFuncAttributeMaxDynamicSharedMemorySize, FLASH_SMEM);
    flash<<<dim3(S_TOT / 64, NH), 256, FLASH_SMEM>>>(Qp, Kp, Vp, Op);

    // output projections on tensor cores
    split_bf16<<<(S_TOT * DMODEL + 255) / 256, 256>>>(Op, OhiP, OloP, S_TOT * DMODEL);
    cudaFuncSetAttribute(out_mma, cudaFuncAttributeMaxDynamicSharedMemorySize, GEMM_SMEM);
    out_mma<<<dim3(12, 20), 256, GEMM_SMEM>>>(OhiP, OloP, WhiP, WloP, bo, bao, out);
}

// round 12
// speedup vs baseline: 2.9950x; 1.8216x over previous
#include <cuda_runtime.h>
#include <cuda_bf16.h>
#include <cstddef>
#include <cstdint>

#define S_IMG  2048
#define S_TXT  512
#define S_TOT  2560
#define DMODEL 1536
#define NH     24
#define DH     64

typedef unsigned long long ull;

// ---------------- scratch (no allocations allowed) ----------------
#define WSZ (DMODEL * DMODEL)
#define QKVN (NH * S_TOT * DH)
__device__ float g_Q[QKVN];                                   // [h][s][d] fp32
__device__ float g_K[QKVN];
__device__ float g_V[QKVN];
__device__ float g_O[S_TOT * DMODEL];                         // [s][h*64+d]
__device__ __align__(16) __nv_bfloat16 g_Whi[8 * WSZ];
__device__ __align__(16) __nv_bfloat16 g_Wlo[8 * WSZ];
__device__ __align__(16) __nv_bfloat16 g_Xhi[S_TOT * DMODEL];
__device__ __align__(16) __nv_bfloat16 g_Xlo[S_TOT * DMODEL];
__device__ __align__(16) __nv_bfloat16 g_Ohi[S_TOT * DMODEL];
__device__ __align__(16) __nv_bfloat16 g_Olo[S_TOT * DMODEL];
__device__ __align__(16) __nv_bfloat16 g_Qhi[QKVN], g_Qlo[QKVN];   // [h][s][d], x0.125
__device__ __align__(16) __nv_bfloat16 g_Khi[QKVN], g_Klo[QKVN];   // [h][s][d]
__device__ __align__(16) __nv_bfloat16 g_Vthi[QKVN], g_Vtlo[QKVN]; // [h][d][s]

// ---------------- helpers ----------------
__device__ __forceinline__ unsigned smem_u32(const void* p) {
    unsigned a;
    asm("{ .reg .u64 t; cvta.to.shared.u64 t, %1; cvt.u32.u64 %0, t; }" : "=r"(a) : "l"(p));
    return a;
}
__device__ __forceinline__ void cp16(unsigned dst, const void* src) {
    asm volatile("cp.async.cg.shared.global [%0], [%1], 16;" :: "r"(dst), "l"(src) : "memory");
}
__device__ __forceinline__ uint32_t lds_bf2(const __nv_bfloat16* base, int elem) {
    return *(const uint32_t*)(base + elem);
}
__device__ __forceinline__ void mma16816(float* c, const uint32_t* a, uint32_t b0, uint32_t b1) {
    asm volatile(
        "mma.sync.aligned.m16n8k16.row.col.f32.bf16.bf16.f32 "
        "{%0,%1,%2,%3}, {%4,%5,%6,%7}, {%8,%9}, {%0,%1,%2,%3};"
        : "+f"(c[0]), "+f"(c[1]), "+f"(c[2]), "+f"(c[3])
        : "r"(a[0]), "r"(a[1]), "r"(a[2]), "r"(a[3]), "r"(b0), "r"(b1));
}
__device__ __forceinline__ uint32_t bfpair(float lo, float hi) {   // reg.lo=lo, reg.hi=hi
    uint32_t r; asm("cvt.rn.bf16x2.f32 %0, %1, %2;" : "=r"(r) : "f"(hi), "f"(lo)); return r;
}
__device__ __forceinline__ float bfround(float x) {
    return __bfloat162float(__float2bfloat16(x));
}

// ---------------- splits ----------------
__global__ void split4(const float* __restrict__ src, __nv_bfloat16* __restrict__ hi,
                       __nv_bfloat16* __restrict__ lo, int n4)
{
    int i = blockIdx.x * 256 + threadIdx.x;
    if (i < n4) {
        float4 v = ((const float4*)src)[i];
        __nv_bfloat162 h0{__float2bfloat16(v.x), __float2bfloat16(v.y)};
        __nv_bfloat162 h1{__float2bfloat16(v.z), __float2bfloat16(v.w)};
        ((__nv_bfloat162*)hi)[2 * i]     = h0;
        ((__nv_bfloat162*)hi)[2 * i + 1] = h1;
        __nv_bfloat162 l0{__float2bfloat16(v.x - __bfloat162float(h0.x)),
                          __float2bfloat16(v.y - __bfloat162float(h0.y))};
        __nv_bfloat162 l1{__float2bfloat16(v.z - __bfloat162float(h1.x)),
                          __float2bfloat16(v.w - __bfloat162float(h1.y))};
        ((__nv_bfloat162*)lo)[2 * i]     = l0;
        ((__nv_bfloat162*)lo)[2 * i + 1] = l1;
    }
}

// all 8 weights in one launch; blockIdx.y selects the weight
__global__ void splitW(const float* w0, const float* w1, const float* w2, const float* w3,
                       const float* w4, const float* w5, const float* w6, const float* w7,
                       __nv_bfloat16* __restrict__ hi, __nv_bfloat16* __restrict__ lo)
{
    const float* ws[8] = {w0, w1, w2, w3, w4, w5, w6, w7};
    const int wsel = blockIdx.y;
    const float* src = ws[wsel];
    int i = blockIdx.x * 256 + threadIdx.x;          // over WSZ/4
    if (i < WSZ / 4) {
        float4 v = ((const float4*)src)[i];
        const size_t o2 = (size_t)wsel * (WSZ / 2) + 2 * i;
        __nv_bfloat162 h0{__float2bfloat16(v.x), __float2bfloat16(v.y)};
        __nv_bfloat162 h1{__float2bfloat16(v.z), __float2bfloat16(v.w)};
        ((__nv_bfloat162*)hi)[o2]     = h0;
        ((__nv_bfloat162*)hi)[o2 + 1] = h1;
        __nv_bfloat162 l0{__float2bfloat16(v.x - __bfloat162float(h0.x)),
                          __float2bfloat16(v.y - __bfloat162float(h0.y))};
        __nv_bfloat162 l1{__float2bfloat16(v.z - __bfloat162float(h1.x)),
                          __float2bfloat16(v.w - __bfloat162float(h1.y))};
        ((__nv_bfloat162*)lo)[o2]     = l0;
        ((__nv_bfloat162*)lo)[o2 + 1] = l1;
    }
}

// Q (x0.125) and K split; blockIdx.y: 0=Q, 1=K
__global__ void qksplit(const float* __restrict__ Q, const float* __restrict__ K,
                        __nv_bfloat16* Qh, __nv_bfloat16* Ql,
                        __nv_bfloat16* Kh, __nv_bfloat16* Kl)
{
    const bool isK = blockIdx.y;
    const float sc = isK ? 1.0f : 0.125f;
    const float* src = isK ? K : Q;
    __nv_bfloat16* dh = isK ? Kh : Qh;
    __nv_bfloat16* dl = isK ? Kl : Ql;
    int i = blockIdx.x * 256 + threadIdx.x;          // over QKVN/2
    float2 v = ((const float2*)src)[i];
    v.x *= sc; v.y *= sc;
    __nv_bfloat162 h{__float2bfloat16(v.x), __float2bfloat16(v.y)};
    ((__nv_bfloat162*)dh)[i] = h;
    ((__nv_bfloat162*)dl)[i] = __nv_bfloat162{
        __float2bfloat16(v.x - __bfloat162float(h.x)),
        __float2bfloat16(v.y - __bfloat162float(h.y))};
}

// V transpose+split: [h][s][d] fp32 -> [h][d][s] bf16 hi/lo
__global__ void vtsplit(const float* __restrict__ V,
                        __nv_bfloat16* __restrict__ Vth, __nv_bfloat16* __restrict__ Vtl)
{
    __shared__ float t[32][33];
    const int h = blockIdx.z;
    const int s0 = blockIdx.x * 32, d0 = blockIdx.y * 32;
    const int tx = threadIdx.x, ty = threadIdx.y;    // 32 x 8
    const float* Vh_ = V + (size_t)h * S_TOT * DH;
    #pragma unroll
    for (int j = 0; j < 4; j++)
        t[ty + 8 * j][tx] = Vh_[(size_t)(s0 + ty + 8 * j) * DH + d0 + tx];
    __syncthreads();
    __nv_bfloat16* oh = Vth + (size_t)h * DH * S_TOT;
    __nv_bfloat16* ol = Vtl + (size_t)h * DH * S_TOT;
    #pragma unroll
    for (int j = 0; j < 4; j++) {
        const float v = t[tx][ty + 8 * j];
        const __nv_bfloat16 hh = __float2bfloat16(v);
        const size_t o = (size_t)(d0 + ty + 8 * j) * S_TOT + s0 + tx;
        oh[o] = hh;
        ol[o] = __float2bfloat16(v - __bfloat162float(hh));
    }
}

// ================= warp-MMA bf16 GEMM (round-11, validated) =================
#define GBK      32
#define GSTRIDE  40
#define GBUF     (128 * GSTRIDE * 2)
#define GSTAGE   (4 * GBUF)
#define GEMM_SMEM (2 * GSTAGE)

__device__ void mma_core(const __nv_bfloat16* __restrict__ Ah, const __nv_bfloat16* __restrict__ Al,
                         const __nv_bfloat16* __restrict__ Wh, const __nv_bfloat16* __restrict__ Wl,
                         char* smem, float acc[2][8][4])
{
    const int tid  = threadIdx.x;
    const int lane = tid & 31;
    const int wid  = tid >> 5;
    const int Rm   = (wid & 3) * 32;
    const int Cn   = (wid >> 2) * 64;
    const int gp   = lane >> 2;
    const int qd   = lane & 3;

    const unsigned sb = smem_u32(smem);
    const __nv_bfloat16* gsrc[4] = {Ah, Al, Wh, Wl};

    auto issue = [&](int c, int stage) {
        #pragma unroll
        for (int t4 = 0; t4 < 4; t4++) {
            const __nv_bfloat16* s = gsrc[t4] + c * GBK;
            const unsigned dbase = sb + stage * GSTAGE + t4 * GBUF;
            #pragma unroll
            for (int i = 0; i < 2; i++) {
                const int idx = tid + i * 256;
                const int row = idx >> 2, cg = idx & 3;
                cp16(dbase + (row * GSTRIDE + cg * 8) * 2,
                     s + (size_t)row * DMODEL + cg * 8);
            }
        }
        asm volatile("cp.async.commit_group;" ::: "memory");
    };

    #pragma unroll
    for (int mi = 0; mi < 2; mi++)
        #pragma unroll
        for (int ni = 0; ni < 8; ni++)
            #pragma unroll
            for (int j = 0; j < 4; j++) acc[mi][ni][j] = 0.0f;

    issue(0, 0);

    for (int c = 0; c < DMODEL / GBK; c++) {
        asm volatile("cp.async.wait_group 0;" ::: "memory");
        __syncthreads();
        if (c + 1 < DMODEL / GBK) issue(c + 1, (c + 1) & 1);

        const char* st = smem + (c & 1) * GSTAGE;
        const __nv_bfloat16* sAh = (const __nv_bfloat16*)(st);
        const __nv_bfloat16* sAl = (const __nv_bfloat16*)(st + GBUF);
        const __nv_bfloat16* sWh = (const __nv_bfloat16*)(st + 2 * GBUF);
        const __nv_bfloat16* sWl = (const __nv_bfloat16*)(st + 3 * GBUF);

        #pragma unroll
        for (int k0 = 0; k0 < GBK; k0 += 16) {
            uint32_t ah[2][4], al[2][4];
            #pragma unroll
            for (int mi = 0; mi < 2; mi++) {
                const int r = Rm + mi * 16 + gp;
                const int k = k0 + qd * 2;
                ah[mi][0] = lds_bf2(sAh, r * GSTRIDE + k);
                ah[mi][1] = lds_bf2(sAh, (r + 8) * GSTRIDE + k);
                ah[mi][2] = lds_bf2(sAh, r * GSTRIDE + k + 8);
                ah[mi][3] = lds_bf2(sAh, (r + 8) * GSTRIDE + k + 8);
                al[mi][0] = lds_bf2(sAl, r * GSTRIDE + k);
                al[mi][1] = lds_bf2(sAl, (r + 8) * GSTRIDE + k);
                al[mi][2] = lds_bf2(sAl, r * GSTRIDE + k + 8);
                al[mi][3] = lds_bf2(sAl, (r + 8) * GSTRIDE + k + 8);
            }
            #pragma unroll
            for (int ni = 0; ni < 8; ni++) {
                const int n = Cn + ni * 8 + gp;
                const int k = k0 + qd * 2;
                const uint32_t bh0 = lds_bf2(sWh, n * GSTRIDE + k);
                const uint32_t bh1 = lds_bf2(sWh, n * GSTRIDE + k + 8);
                const uint32_t bl0 = lds_bf2(sWl, n * GSTRIDE + k);
                const uint32_t bl1 = lds_bf2(sWl, n * GSTRIDE + k + 8);
                #pragma unroll
                for (int mi = 0; mi < 2; mi++) {
                    mma16816(acc[mi][ni], ah[mi], bh0, bh1);
                    mma16816(acc[mi][ni], ah[mi], bl0, bl1);
                    mma16816(acc[mi][ni], al[mi], bh0, bh1);
                }
            }
        }
    }
}

__global__ __launch_bounds__(256)
void qkv_mma(const __nv_bfloat16* __restrict__ Xhi, const __nv_bfloat16* __restrict__ Xlo,
             const __nv_bfloat16* __restrict__ Whi8, const __nv_bfloat16* __restrict__ Wlo8,
             const float* __restrict__ bq, const float* __restrict__ bk, const float* __restrict__ bv,
             const float* __restrict__ baq, const float* __restrict__ bak, const float* __restrict__ bav,
             float* __restrict__ Qp, float* __restrict__ Kp, float* __restrict__ Vp)
{
    extern __shared__ __align__(16) char smem[];
    const int bx = blockIdx.x, mt = blockIdx.y;
    const int proj = bx / 12;
    const int n0b  = (bx % 12) * 128;
    const bool txt = (mt < 4);
    const int widx = (txt ? 3 : 0) + proj;

    const __nv_bfloat16* Ah = Xhi + (size_t)mt * 128 * DMODEL;
    const __nv_bfloat16* Al = Xlo + (size_t)mt * 128 * DMODEL;
    const __nv_bfloat16* Wh = Whi8 + (size_t)widx * WSZ + (size_t)n0b * DMODEL;
    const __nv_bfloat16* Wl = Wlo8 + (size_t)widx * WSZ + (size_t)n0b * DMODEL;
    const float* bias = txt ? (proj == 0 ? baq : proj == 1 ? bak : bav)
                            : (proj == 0 ? bq  : proj == 1 ? bk  : bv);
    float* out = proj == 0 ? Qp : proj == 1 ? Kp : Vp;

    float acc[2][8][4];
    mma_core(Ah, Al, Wh, Wl, smem, acc);

    const int lane = threadIdx.x & 31, wid = threadIdx.x >> 5;
    const int Rm = (wid & 3) * 32, Cn = (wid >> 2) * 64;
    const int gp = lane >> 2, qd = lane & 3;

    #pragma unroll
    for (int ni = 0; ni < 8; ni++) {
        const int n0 = n0b + Cn + ni * 8;
        const int h = n0 >> 6, d0 = (n0 & 63) + qd * 2;
        const float2 bb = *(const float2*)&bias[n0 + qd * 2];
        #pragma unroll
        for (int mi = 0; mi < 2; mi++) {
            const int s = mt * 128 + Rm + mi * 16 + gp;
            float* p0 = out + (((size_t)h * S_TOT + s) << 6) + d0;
            float* p1 = out + (((size_t)h * S_TOT + s + 8) << 6) + d0;
            *(float2*)p0 = make_float2(acc[mi][ni][0] + bb.x, acc[mi][ni][1] + bb.y);
            *(float2*)p1 = make_float2(acc[mi][ni][2] + bb.x, acc[mi][ni][3] + bb.y);
        }
    }
}

__global__ __launch_bounds__(256)
void out_mma(const __nv_bfloat16* __restrict__ Ohi, const __nv_bfloat16* __restrict__ Olo,
             const __nv_bfloat16* __restrict__ Whi8, const __nv_bfloat16* __restrict__ Wlo8,
             const float* __restrict__ bo, const float* __restrict__ bao,
             float* __restrict__ out)
{
    extern __shared__ __align__(16) char smem[];
    const int nt = blockIdx.x, mt = blockIdx.y;
    const int r0 = mt * 128;
    const bool img = (r0 < S_IMG);
    const size_t arow = img ? (size_t)(S_TXT + r0) : (size_t)(r0 - S_IMG);
    const int widx = img ? 6 : 7;

    const __nv_bfloat16* Ah = Ohi + arow * DMODEL;
    const __nv_bfloat16* Al = Olo + arow * DMODEL;
    const __nv_bfloat16* Wh = Whi8 + (size_t)widx * WSZ + (size_t)nt * 128 * DMODEL;
    const __nv_bfloat16* Wl = Wlo8 + (size_t)widx * WSZ + (size_t)nt * 128 * DMODEL;
    const float* bias = img ? bo : bao;

    float acc[2][8][4];
    mma_core(Ah, Al, Wh, Wl, smem, acc);

    const int lane = threadIdx.x & 31, wid = threadIdx.x >> 5;
    const int Rm = (wid & 3) * 32, Cn = (wid >> 2) * 64;
    const int gp = lane >> 2, qd = lane & 3;

    #pragma unroll
    for (int ni = 0; ni < 8; ni++) {
        const int n0 = nt * 128 + Cn + ni * 8 + qd * 2;
        const float2 bb = *(const float2*)&bias[n0];
        #pragma unroll
        for (int mi = 0; mi < 2; mi++) {
            const int m = r0 + Rm + mi * 16 + gp;
            *(float2*)(out + (size_t)m * DMODEL + n0) =
                make_float2(acc[mi][ni][0] + bb.x, acc[mi][ni][1] + bb.y);
            *(float2*)(out + (size_t)(m + 8) * DMODEL + n0) =
                make_float2(acc[mi][ni][2] + bb.x, acc[mi][ni][3] + bb.y);
        }
    }
}

// ---------------- RMS-norm + gain + RoPE (unchanged) ----------------
__global__ __launch_bounds__(128)
void rmsrope(float* __restrict__ buf, const float* __restrict__ g_txt,
             const float* __restrict__ g_img, const float* __restrict__ rcos,
             const float* __restrict__ rsin)
{
    const int warp = threadIdx.x >> 5;
    const int lane = threadIdx.x & 31;
    const int row  = blockIdx.x * 4 + warp;
    const int s    = row % S_TOT;

    float2 x = *(float2*)&buf[(size_t)row * 64 + lane * 2];
    float ss = x.x * x.x + x.y * x.y;
    #pragma unroll
    for (int off = 16; off > 0; off >>= 1)
        ss += __shfl_xor_sync(0xffffffffu, ss, off);
    const float r = rsqrtf(ss * (1.0f / 64.0f) + 1e-6f);

    const float* g = (s < S_TXT) ? g_txt : g_img;
    const float y0 = x.x * r * g[lane * 2];
    const float y1 = x.y * r * g[lane * 2 + 1];
    const float c  = rcos[s * 64 + lane * 2];
    const float sn = rsin[s * 64 + lane * 2];
    *(float2*)&buf[(size_t)row * 64 + lane * 2] =
        make_float2(y0 * c - y1 * sn, y1 * c + y0 * sn);
}

// ================= tensor-core flash attention =================
// grid (40, 24), 256 threads = 8 warps: qw = wid&3 (16 q-rows each), kw = wid>>2 (32 k-cols each).
// Q/K/V pre-split bf16 (Q scaled 0.125). No-max softmax (|s|<=8). O fp32 frags, 40 k-tiles.
// Smem: Qh,Ql [64][72] once; stages: Kh,Kl,Vth,Vtl [64][72] double-buffered.
#define FSTRIDE 72
#define FTILE   (64 * FSTRIDE * 2)     // 9216 B
#define FL_Q    0
#define FL_ST   (2 * FTILE)            // 18432
#define FL_STG  (4 * FTILE)            // 36864
#define FLASH2_SMEM (FL_ST + 2 * FL_STG)  // 92160

__global__ __launch_bounds__(256)
void flash_mma(const __nv_bfloat16* __restrict__ Qh_g, const __nv_bfloat16* __restrict__ Ql_g,
               const __nv_bfloat16* __restrict__ Kh_g, const __nv_bfloat16* __restrict__ Kl_g,
               const __nv_bfloat16* __restrict__ Vth_g, const __nv_bfloat16* __restrict__ Vtl_g,
               float* __restrict__ O)
{
    extern __shared__ __align__(16) char smem[];
    const int tid = threadIdx.x, lane = tid & 31, wid = tid >> 5;
    const int qw = wid & 3, kw = wid >> 2;
    const int gp = lane >> 2, qd = lane & 3;
    const int h = blockIdx.y, q0 = blockIdx.x * 64;
    const unsigned sb = smem_u32(smem);

    const size_t hb  = (size_t)h * S_TOT * DH;    // Q,K [h][s][d]
    const size_t hbT = (size_t)h * DH * S_TOT;    // Vt  [h][d][s]

    // stage Q once
    {
        const __nv_bfloat16* src[2] = {Qh_g + hb + (size_t)q0 * DH, Ql_g + hb + (size_t)q0 * DH};
        #pragma unroll
        for (int t = 0; t < 2; t++) {
            const unsigned db = sb + FL_Q + t * FTILE;
            for (int i = tid; i < 512; i += 256) {
                const int row = i >> 3, cg = i & 7;
                cp16(db + (row * FSTRIDE + cg * 8) * 2, src[t] + (size_t)row * DH + cg * 8);
            }
        }
        asm volatile("cp.async.commit_group;" ::: "memory");
    }

    auto issueKV = [&](int kt, int stage) {
        const __nv_bfloat16* src[4] = {
            Kh_g  + hb  + (size_t)(kt * 64) * DH,
            Kl_g  + hb  + (size_t)(kt * 64) * DH,
            Vth_g + hbT + kt * 64,
            Vtl_g + hbT + kt * 64};
        #pragma unroll
        for (int t = 0; t < 4; t++) {
            const unsigned db = sb + FL_ST + stage * FL_STG + t * FTILE;
            const size_t rs = (t < 2) ? (size_t)DH : (size_t)S_TOT;
            for (int i = tid; i < 512; i += 256) {
                const int row = i >> 3, cg = i & 7;
                cp16(db + (row * FSTRIDE + cg * 8) * 2, src[t] + (size_t)row * rs + cg * 8);
            }
        }
        asm volatile("cp.async.commit_group;" ::: "memory");
    };

    issueKV(0, 0);

    float oacc[8][4];
    #pragma unroll
    for (int ni = 0; ni < 8; ni++)
        #pragma unroll
        for (int j = 0; j < 4; j++) oacc[ni][j] = 0.0f;
    float lpart[2] = {0.0f, 0.0f};

    const __nv_bfloat16* sQh = (const __nv_bfloat16*)(smem + FL_Q);
    const __nv_bfloat16* sQl = (const __nv_bfloat16*)(smem + FL_Q + FTILE);

    for (int kt = 0; kt < S_TOT / 64; kt++) {
        asm volatile("cp.async.wait_group 0;" ::: "memory");
        __syncthreads();
        if (kt + 1 < S_TOT / 64) issueKV(kt + 1, (kt + 1) & 1);

        const char* st = smem + FL_ST + (kt & 1) * FL_STG;
        const __nv_bfloat16* sKh = (const __nv_bfloat16*)(st);
        const __nv_bfloat16* sKl = (const __nv_bfloat16*)(st + FTILE);
        const __nv_bfloat16* sVh = (const __nv_bfloat16*)(st + 2 * FTILE);
        const __nv_bfloat16* sVl = (const __nv_bfloat16*)(st + 3 * FTILE);

        // ---- S = Q K^T (3-term) ----
        float sacc[4][4];
        #pragma unroll
        for (int ni = 0; ni < 4; ni++)
            #pragma unroll
            for (int j = 0; j < 4; j++) sacc[ni][j] = 0.0f;

        #pragma unroll
        for (int k0 = 0; k0 < 64; k0 += 16) {
            const int r = qw * 16 + gp;
            const int k = k0 + qd * 2;
            uint32_t ah[4], al[4];
            ah[0] = lds_bf2(sQh, r * FSTRIDE + k);
            ah[1] = lds_bf2(sQh, (r + 8) * FSTRIDE + k);
            ah[2] = lds_bf2(sQh, r * FSTRIDE + k + 8);
            ah[3] = lds_bf2(sQh, (r + 8) * FSTRIDE + k + 8);
            al[0] = lds_bf2(sQl, r * FSTRIDE + k);
            al[1] = lds_bf2(sQl, (r + 8) * FSTRIDE + k);
            al[2] = lds_bf2(sQl, r * FSTRIDE + k + 8);
            al[3] = lds_bf2(sQl, (r + 8) * FSTRIDE + k + 8);
            #pragma unroll
            for (int ni = 0; ni < 4; ni++) {
                const int n = kw * 32 + ni * 8 + gp;
                const uint32_t bh0 = lds_bf2(sKh, n * FSTRIDE + k);
                const uint32_t bh1 = lds_bf2(sKh, n * FSTRIDE + k + 8);
                const uint32_t bl0 = lds_bf2(sKl, n * FSTRIDE + k);
                const uint32_t bl1 = lds_bf2(sKl, n * FSTRIDE + k + 8);
                mma16816(sacc[ni], ah, bh0, bh1);
                mma16816(sacc[ni], ah, bl0, bl1);
                mma16816(sacc[ni], al, bh0, bh1);
            }
        }

        // ---- exp (no max: |s|<=8), build P hi/lo A-fragments in registers ----
        uint32_t pA[2][4], plA[2][4];
        #pragma unroll
        for (int ni = 0; ni < 4; ni++) {
            const float p0 = __expf(sacc[ni][0]), p1 = __expf(sacc[ni][1]);
            const float p2 = __expf(sacc[ni][2]), p3 = __expf(sacc[ni][3]);
            lpart[0] += p0 + p1;
            lpart[1] += p2 + p3;
            const int kc = ni >> 1, half = (ni & 1) << 1;
            pA[kc][half]      = bfpair(p0, p1);
            pA[kc][half + 1]  = bfpair(p2, p3);
            plA[kc][half]     = bfpair(p0 - bfround(p0), p1 - bfround(p1));
            plA[kc][half + 1] = bfpair(p2 - bfround(p2), p3 - bfround(p3));
        }

        // ---- O += P V (3-term), B = Vt[d][kpos] ----
        #pragma unroll
        for (int kc = 0; kc < 2; kc++) {
            const int kk = kw * 32 + kc * 16 + qd * 2;
            #pragma unroll
            for (int ni = 0; ni < 8; ni++) {
                const int n = ni * 8 + gp;
                const uint32_t bh0 = lds_bf2(sVh, n * FSTRIDE + kk);
                const uint32_t bh1 = lds_bf2(sVh, n * FSTRIDE + kk + 8);
                const uint32_t bl0 = lds_bf2(sVl, n * FSTRIDE + kk);
                const uint32_t bl1 = lds_bf2(sVl, n * FSTRIDE + kk + 8);
                mma16816(oacc[ni], pA[kc], bh0, bh1);
                mma16816(oacc[ni], pA[kc], bl0, bl1);
                mma16816(oacc[ni], plA[kc], bh0, bh1);
            }
        }
    }

    // ---- final reduction across k-warps + 1/l scaling ----
    __syncthreads();                                   // done with stage smem
    float* ored = (float*)(smem + FL_ST);              // [4][16] rows x stride 68
    float* lred = (float*)(smem + FL_ST + 4 * 16 * 68 * 4);

    #pragma unroll
    for (int off = 1; off < 4; off <<= 1) {
        lpart[0] += __shfl_xor_sync(0xffffffffu, lpart[0], off);
        lpart[1] += __shfl_xor_sync(0xffffffffu, lpart[1], off);
    }
    if (qd == 0) {
        lred[(kw * 4 + qw) * 16 + gp]     = lpart[0];
        lred[(kw * 4 + qw) * 16 + gp + 8] = lpart[1];
    }
    if (kw == 1) {
        #pragma unroll
        for (int ni = 0; ni < 8; ni++) {
            *(float2*)&ored[(qw * 16 + gp) * 68 + ni * 8 + 2 * qd] =
                make_float2(oacc[ni][0], oacc[ni][1]);
            *(float2*)&ored[(qw * 16 + gp + 8) * 68 + ni * 8 + 2 * qd] =
                make_float2(oacc[ni][2], oacc[ni][3]);
        }
    }
    __syncthreads();
    if (kw == 0) {
        const float inv0 = 1.0f / (lred[qw * 16 + gp]     + lred[(4 + qw) * 16 + gp]);
        const float inv1 = 1.0f / (lred[qw * 16 + gp + 8] + lred[(4 + qw) * 16 + gp + 8]);
        #pragma unroll
        for (int ni = 0; ni < 8; ni++) {
            const float2 a = *(const float2*)&ored[(qw * 16 + gp) * 68 + ni * 8 + 2 * qd];
            const float2 b = *(const float2*)&ored[(qw * 16 + gp + 8) * 68 + ni * 8 + 2 * qd];
            const int col = h * 64 + ni * 8 + 2 * qd;
            *(float2*)&O[(size_t)(q0 + qw * 16 + gp) * DMODEL + col] =
                make_float2((oacc[ni][0] + a.x) * inv0, (oacc[ni][1] + a.y) * inv0);
            *(float2*)&O[(size_t)(q0 + qw * 16 + gp + 8) * DMODEL + col] =
                make_float2((oacc[ni][2] + b.x) * inv1, (oacc[ni][3] + b.y) * inv1);
        }
    }
}

// ---------------- launch ----------------
extern "C" void kernel_launch(void* const* d_in, const int* in_sizes, int n_in,
                              void* d_out, int out_size)
{
    const float* hid  = (const float*)d_in[0];
    const float* enc  = (const float*)d_in[1];
    const float* rcos = (const float*)d_in[2];
    const float* rsin = (const float*)d_in[3];
    const float* Wq  = (const float*)d_in[4];  const float* bq  = (const float*)d_in[5];
    const float* Wk  = (const float*)d_in[6];  const float* bk  = (const float*)d_in[7];
    const float* Wv  = (const float*)d_in[8];  const float* bv  = (const float*)d_in[9];
    const float* Waq = (const float*)d_in[10]; const float* baq = (const float*)d_in[11];
    const float* Wak = (const float*)d_in[12]; const float* bak = (const float*)d_in[13];
    const float* Wav = (const float*)d_in[14]; const float* bav = (const float*)d_in[15];
    const float* Wo  = (const float*)d_in[16]; const float* bo  = (const float*)d_in[17];
    const float* Wao = (const float*)d_in[18]; const float* bao = (const float*)d_in[19];
    const float* gq  = (const float*)d_in[20]; const float* gk  = (const float*)d_in[21];
    const float* gaq = (const float*)d_in[22]; const float* gak = (const float*)d_in[23];
    float* out = (float*)d_out;

    float *Qp, *Kp, *Vp, *Op;
    cudaGetSymbolAddress((void**)&Qp, g_Q);
    cudaGetSymbolAddress((void**)&Kp, g_K);
    cudaGetSymbolAddress((void**)&Vp, g_V);
    cudaGetSymbolAddress((void**)&Op, g_O);
    __nv_bfloat16 *WhiP, *WloP, *XhiP, *XloP, *OhiP, *OloP;
    __nv_bfloat16 *QhP, *QlP, *KhP, *KlP, *VthP, *VtlP;
    cudaGetSymbolAddress((void**)&WhiP, g_Whi);
    cudaGetSymbolAddress((void**)&WloP, g_Wlo);
    cudaGetSymbolAddress((void**)&XhiP, g_Xhi);
    cudaGetSymbolAddress((void**)&XloP, g_Xlo);
    cudaGetSymbolAddress((void**)&OhiP, g_Ohi);
    cudaGetSymbolAddress((void**)&OloP, g_Olo);
    cudaGetSymbolAddress((void**)&QhP, g_Qhi);
    cudaGetSymbolAddress((void**)&QlP, g_Qlo);
    cudaGetSymbolAddress((void**)&KhP, g_Khi);
    cudaGetSymbolAddress((void**)&KlP, g_Klo);
    cudaGetSymbolAddress((void**)&VthP, g_Vthi);
    cudaGetSymbolAddress((void**)&VtlP, g_Vtlo);

    // splits: weights (one launch) + activations
    splitW<<<dim3((WSZ / 4 + 255) / 256, 8), 256>>>(Wq, Wk, Wv, Waq, Wak, Wav, Wo, Wao, WhiP, WloP);
    split4<<<(S_TXT * DMODEL / 4 + 255) / 256, 256>>>(enc, XhiP, XloP, S_TXT * DMODEL / 4);
    split4<<<(S_IMG * DMODEL / 4 + 255) / 256, 256>>>(hid, XhiP + (size_t)S_TXT * DMODEL,
                                                      XloP + (size_t)S_TXT * DMODEL, S_IMG * DMODEL / 4);

    // QKV projections (tensor cores) -> fp32 [h][s][d]
    cudaFuncSetAttribute(qkv_mma, cudaFuncAttributeMaxDynamicSharedMemorySize, GEMM_SMEM);
    qkv_mma<<<dim3(36, 20), 256, GEMM_SMEM>>>(XhiP, XloP, WhiP, WloP,
                                              bq, bk, bv, baq, bak, bav, Qp, Kp, Vp);

    // RMS norm + gain + RoPE (fp32 in place)
    rmsrope<<<NH * S_TOT / 4, 128>>>(Qp, gaq, gq, rcos, rsin);
    rmsrope<<<NH * S_TOT / 4, 128>>>(Kp, gak, gk, rcos, rsin);

    // bf16 splits for attention: Q (x0.125), K, V (transposed)
    qksplit<<<dim3(QKVN / 2 / 256, 2), 256>>>(Qp, Kp, QhP, QlP, KhP, KlP);
    vtsplit<<<dim3(S_TOT / 32, DH / 32, NH), dim3(32, 8)>>>(Vp, VthP, VtlP);

    // tensor-core flash attention -> O[s][h*64+d]
    cudaFuncSetAttribute(flash_mma, cudaFuncAttributeMaxDynamicSharedMemorySize, FLASH2_SMEM);
    flash_mma<<<dim3(S_TOT / 64, NH), 256, FLASH2_SMEM>>>(QhP, QlP, KhP, KlP, VthP, VtlP, Op);

    // output projections (tensor cores)
    split4<<<(S_TOT * DMODEL / 4 + 255) / 256, 256>>>(Op, OhiP, OloP, S_TOT * DMODEL / 4);
    cudaFuncSetAttribute(out_mma, cudaFuncAttributeMaxDynamicSharedMemorySize, GEMM_SMEM);
    out_mma<<<dim3(12, 20), 256, GEMM_SMEM>>>(OhiP, OloP, WhiP, WloP, bo, bao, out);
}

// round 13
// speedup vs baseline: 3.4315x; 1.1457x over previous
#include <cuda_runtime.h>
#include <cuda_bf16.h>
#include <cstddef>
#include <cstdint>

#define S_IMG  2048
#define S_TXT  512
#define S_TOT  2560
#define DMODEL 1536
#define NH     24
#define DH     64

typedef unsigned long long ull;

// ---------------- scratch (no allocations allowed) ----------------
#define WSZ (DMODEL * DMODEL)
#define QKVN (NH * S_TOT * DH)
__device__ float g_Q[QKVN];                                   // [h][s][d] fp32 (pre-norm)
__device__ float g_K[QKVN];
__device__ float g_V[QKVN];
__device__ __align__(16) __nv_bfloat16 g_Whi[8 * WSZ];
__device__ __align__(16) __nv_bfloat16 g_Wlo[8 * WSZ];
__device__ __align__(16) __nv_bfloat16 g_Xhi[S_TOT * DMODEL];
__device__ __align__(16) __nv_bfloat16 g_Xlo[S_TOT * DMODEL];
__device__ __align__(16) __nv_bfloat16 g_Ohi[S_TOT * DMODEL]; // [s][h*64+d]
__device__ __align__(16) __nv_bfloat16 g_Olo[S_TOT * DMODEL];
__device__ __align__(16) __nv_bfloat16 g_Qhi[QKVN], g_Qlo[QKVN];   // [h][s][d], x0.125
__device__ __align__(16) __nv_bfloat16 g_Khi[QKVN], g_Klo[QKVN];   // [h][s][d]
__device__ __align__(16) __nv_bfloat16 g_Vthi[QKVN], g_Vtlo[QKVN]; // [h][d][s]

// ---------------- helpers ----------------
__device__ __forceinline__ unsigned smem_u32(const void* p) {
    unsigned a;
    asm("{ .reg .u64 t; cvta.to.shared.u64 t, %1; cvt.u32.u64 %0, t; }" : "=r"(a) : "l"(p));
    return a;
}
__device__ __forceinline__ void cp16(unsigned dst, const void* src) {
    asm volatile("cp.async.cg.shared.global [%0], [%1], 16;" :: "r"(dst), "l"(src) : "memory");
}
__device__ __forceinline__ void ldsm4(uint32_t* r, unsigned a) {
    asm volatile("ldmatrix.sync.aligned.m8n8.x4.shared.b16 {%0,%1,%2,%3}, [%4];"
        : "=r"(r[0]), "=r"(r[1]), "=r"(r[2]), "=r"(r[3]) : "r"(a));
}
__device__ __forceinline__ void mma16816(float* c, const uint32_t* a, uint32_t b0, uint32_t b1) {
    asm volatile(
        "mma.sync.aligned.m16n8k16.row.col.f32.bf16.bf16.f32 "
        "{%0,%1,%2,%3}, {%4,%5,%6,%7}, {%8,%9}, {%0,%1,%2,%3};"
        : "+f"(c[0]), "+f"(c[1]), "+f"(c[2]), "+f"(c[3])
        : "r"(a[0]), "r"(a[1]), "r"(a[2]), "r"(a[3]), "r"(b0), "r"(b1));
}
__device__ __forceinline__ uint32_t bfpair(float lo, float hi) {   // reg.lo=lo, reg.hi=hi
    uint32_t r; asm("cvt.rn.bf16x2.f32 %0, %1, %2;" : "=r"(r) : "f"(hi), "f"(lo)); return r;
}
__device__ __forceinline__ float bfround(float x) {
    return __bfloat162float(__float2bfloat16(x));
}

// ---------------- splits ----------------
__global__ void split4(const float* __restrict__ src, __nv_bfloat16* __restrict__ hi,
                       __nv_bfloat16* __restrict__ lo, int n4)
{
    int i = blockIdx.x * 256 + threadIdx.x;
    if (i < n4) {
        float4 v = ((const float4*)src)[i];
        __nv_bfloat162 h0{__float2bfloat16(v.x), __float2bfloat16(v.y)};
        __nv_bfloat162 h1{__float2bfloat16(v.z), __float2bfloat16(v.w)};
        ((__nv_bfloat162*)hi)[2 * i]     = h0;
        ((__nv_bfloat162*)hi)[2 * i + 1] = h1;
        __nv_bfloat162 l0{__float2bfloat16(v.x - __bfloat162float(h0.x)),
                          __float2bfloat16(v.y - __bfloat162float(h0.y))};
        __nv_bfloat162 l1{__float2bfloat16(v.z - __bfloat162float(h1.x)),
                          __float2bfloat16(v.w - __bfloat162float(h1.y))};
        ((__nv_bfloat162*)lo)[2 * i]     = l0;
        ((__nv_bfloat162*)lo)[2 * i + 1] = l1;
    }
}

__global__ void splitW(const float* w0, const float* w1, const float* w2, const float* w3,
                       const float* w4, const float* w5, const float* w6, const float* w7,
                       __nv_bfloat16* __restrict__ hi, __nv_bfloat16* __restrict__ lo)
{
    const float* ws[8] = {w0, w1, w2, w3, w4, w5, w6, w7};
    const int wsel = blockIdx.y;
    const float* src = ws[wsel];
    int i = blockIdx.x * 256 + threadIdx.x;
    if (i < WSZ / 4) {
        float4 v = ((const float4*)src)[i];
        const size_t o2 = (size_t)wsel * (WSZ / 2) + 2 * i;
        __nv_bfloat162 h0{__float2bfloat16(v.x), __float2bfloat16(v.y)};
        __nv_bfloat162 h1{__float2bfloat16(v.z), __float2bfloat16(v.w)};
        ((__nv_bfloat162*)hi)[o2]     = h0;
        ((__nv_bfloat162*)hi)[o2 + 1] = h1;
        __nv_bfloat162 l0{__float2bfloat16(v.x - __bfloat162float(h0.x)),
                          __float2bfloat16(v.y - __bfloat162float(h0.y))};
        __nv_bfloat162 l1{__float2bfloat16(v.z - __bfloat162float(h1.x)),
                          __float2bfloat16(v.w - __bfloat162float(h1.y))};
        ((__nv_bfloat162*)lo)[o2]     = l0;
        ((__nv_bfloat162*)lo)[o2 + 1] = l1;
    }
}

// V transpose+split: [h][s][d] fp32 -> [h][d][s] bf16 hi/lo
__global__ void vtsplit(const float* __restrict__ V,
                        __nv_bfloat16* __restrict__ Vth, __nv_bfloat16* __restrict__ Vtl)
{
    __shared__ float t[32][33];
    const int h = blockIdx.z;
    const int s0 = blockIdx.x * 32, d0 = blockIdx.y * 32;
    const int tx = threadIdx.x, ty = threadIdx.y;
    const float* Vh_ = V + (size_t)h * S_TOT * DH;
    #pragma unroll
    for (int j = 0; j < 4; j++)
        t[ty + 8 * j][tx] = Vh_[(size_t)(s0 + ty + 8 * j) * DH + d0 + tx];
    __syncthreads();
    __nv_bfloat16* oh = Vth + (size_t)h * DH * S_TOT;
    __nv_bfloat16* ol = Vtl + (size_t)h * DH * S_TOT;
    #pragma unroll
    for (int j = 0; j < 4; j++) {
        const float v = t[tx][ty + 8 * j];
        const __nv_bfloat16 hh = __float2bfloat16(v);
        const size_t o = (size_t)(d0 + ty + 8 * j) * S_TOT + s0 + tx;
        oh[o] = hh;
        ol[o] = __float2bfloat16(v - __bfloat162float(hh));
    }
}

// ---------------- RMS-norm + gain + RoPE, fused bf16 hi/lo split ----------------
__global__ __launch_bounds__(128)
void rmsrope_split(const float* __restrict__ buf, const float* __restrict__ g_txt,
                   const float* __restrict__ g_img, const float* __restrict__ rcos,
                   const float* __restrict__ rsin, float scale,
                   __nv_bfloat16* __restrict__ hi, __nv_bfloat16* __restrict__ lo)
{
    const int warp = threadIdx.x >> 5;
    const int lane = threadIdx.x & 31;
    const int row  = blockIdx.x * 4 + warp;
    const int s    = row % S_TOT;

    float2 x = *(const float2*)&buf[(size_t)row * 64 + lane * 2];
    float ss = x.x * x.x + x.y * x.y;
    #pragma unroll
    for (int off = 16; off > 0; off >>= 1)
        ss += __shfl_xor_sync(0xffffffffu, ss, off);
    const float r = rsqrtf(ss * (1.0f / 64.0f) + 1e-6f);

    const float* g = (s < S_TXT) ? g_txt : g_img;
    const float y0 = x.x * r * g[lane * 2];
    const float y1 = x.y * r * g[lane * 2 + 1];
    const float c  = rcos[s * 64 + lane * 2];
    const float sn = rsin[s * 64 + lane * 2];
    const float o0 = (y0 * c - y1 * sn) * scale;
    const float o1 = (y1 * c + y0 * sn) * scale;
    const __nv_bfloat16 h0 = __float2bfloat16(o0);
    const __nv_bfloat16 h1 = __float2bfloat16(o1);
    ((__nv_bfloat162*)hi)[(size_t)row * 32 + lane] = __nv_bfloat162{h0, h1};
    ((__nv_bfloat162*)lo)[(size_t)row * 32 + lane] = __nv_bfloat162{
        __float2bfloat16(o0 - __bfloat162float(h0)),
        __float2bfloat16(o1 - __bfloat162float(h1))};
}

// ================= warp-MMA bf16 GEMM (ldmatrix fragment loads) =================
#define GBK      32
#define GSTRIDE  40
#define GBUF     (128 * GSTRIDE * 2)
#define GSTAGE   (4 * GBUF)
#define GEMM_SMEM (2 * GSTAGE)

__device__ void mma_core(const __nv_bfloat16* __restrict__ Ah, const __nv_bfloat16* __restrict__ Al,
                         const __nv_bfloat16* __restrict__ Wh, const __nv_bfloat16* __restrict__ Wl,
                         char* smem, float acc[2][8][4])
{
    const int tid  = threadIdx.x;
    const int lane = tid & 31;
    const int wid  = tid >> 5;
    const int Rm   = (wid & 3) * 32;
    const int Cn   = (wid >> 2) * 64;
    const int lr   = lane & 7, sel = lane >> 3;
    // ldmatrix per-lane tile offsets (elements)
    const int aOff = ((sel & 1) * 8 + lr) * GSTRIDE + (sel & 2) * 4;   // A: tiles r0,r8 x k0,k8
    const int bOff = ((sel >> 1) * 8 + lr) * GSTRIDE + (sel & 1) * 8;  // B: tiles n,n+8 x k0,k8

    const unsigned sb = smem_u32(smem);
    const __nv_bfloat16* gsrc[4] = {Ah, Al, Wh, Wl};

    auto issue = [&](int c, int stage) {
        #pragma unroll
        for (int t4 = 0; t4 < 4; t4++) {
            const __nv_bfloat16* s = gsrc[t4] + c * GBK;
            const unsigned dbase = sb + stage * GSTAGE + t4 * GBUF;
            #pragma unroll
            for (int i = 0; i < 2; i++) {
                const int idx = tid + i * 256;
                const int row = idx >> 2, cg = idx & 3;
                cp16(dbase + (row * GSTRIDE + cg * 8) * 2,
                     s + (size_t)row * DMODEL + cg * 8);
            }
        }
        asm volatile("cp.async.commit_group;" ::: "memory");
    };

    #pragma unroll
    for (int mi = 0; mi < 2; mi++)
        #pragma unroll
        for (int ni = 0; ni < 8; ni++)
            #pragma unroll
            for (int j = 0; j < 4; j++) acc[mi][ni][j] = 0.0f;

    issue(0, 0);

    for (int c = 0; c < DMODEL / GBK; c++) {
        asm volatile("cp.async.wait_group 0;" ::: "memory");
        __syncthreads();
        if (c + 1 < DMODEL / GBK) issue(c + 1, (c + 1) & 1);

        const unsigned uSt = sb + (c & 1) * GSTAGE;

        #pragma unroll
        for (int k0 = 0; k0 < GBK; k0 += 16) {
            uint32_t ah[2][4], al[2][4];
            #pragma unroll
            for (int mi = 0; mi < 2; mi++) {
                const unsigned ao = uSt + 2u * ((Rm + mi * 16) * GSTRIDE + k0 + aOff);
                ldsm4(ah[mi], ao);
                ldsm4(al[mi], ao + GBUF);
            }
            #pragma unroll
            for (int np = 0; np < 4; np++) {
                uint32_t bh[4], bl[4];
                const unsigned bo = uSt + 2 * GBUF + 2u * ((Cn + np * 16) * GSTRIDE + k0 + bOff);
                ldsm4(bh, bo);
                ldsm4(bl, bo + GBUF);
                #pragma unroll
                for (int mi = 0; mi < 2; mi++) {
                    mma16816(acc[mi][2 * np],     ah[mi], bh[0], bh[1]);
                    mma16816(acc[mi][2 * np],     ah[mi], bl[0], bl[1]);
                    mma16816(acc[mi][2 * np],     al[mi], bh[0], bh[1]);
                    mma16816(acc[mi][2 * np + 1], ah[mi], bh[2], bh[3]);
                    mma16816(acc[mi][2 * np + 1], ah[mi], bl[2], bl[3]);
                    mma16816(acc[mi][2 * np + 1], al[mi], bh[2], bh[3]);
                }
            }
        }
    }
}

__global__ __launch_bounds__(256, 2)
void qkv_mma(const __nv_bfloat16* __restrict__ Xhi, const __nv_bfloat16* __restrict__ Xlo,
             const __nv_bfloat16* __restrict__ Whi8, const __nv_bfloat16* __restrict__ Wlo8,
             const float* __restrict__ bq, const float* __restrict__ bk, const float* __restrict__ bv,
             const float* __restrict__ baq, const float* __restrict__ bak, const float* __restrict__ bav,
             float* __restrict__ Qp, float* __restrict__ Kp, float* __restrict__ Vp)
{
    extern __shared__ __align__(16) char smem[];
    const int bx = blockIdx.x, mt = blockIdx.y;
    const int proj = bx / 12;
    const int n0b  = (bx % 12) * 128;
    const bool txt = (mt < 4);
    const int widx = (txt ? 3 : 0) + proj;

    const __nv_bfloat16* Ah = Xhi + (size_t)mt * 128 * DMODEL;
    const __nv_bfloat16* Al = Xlo + (size_t)mt * 128 * DMODEL;
    const __nv_bfloat16* Wh = Whi8 + (size_t)widx * WSZ + (size_t)n0b * DMODEL;
    const __nv_bfloat16* Wl = Wlo8 + (size_t)widx * WSZ + (size_t)n0b * DMODEL;
    const float* bias = txt ? (proj == 0 ? baq : proj == 1 ? bak : bav)
                            : (proj == 0 ? bq  : proj == 1 ? bk  : bv);
    float* out = proj == 0 ? Qp : proj == 1 ? Kp : Vp;

    float acc[2][8][4];
    mma_core(Ah, Al, Wh, Wl, smem, acc);

    const int lane = threadIdx.x & 31, wid = threadIdx.x >> 5;
    const int Rm = (wid & 3) * 32, Cn = (wid >> 2) * 64;
    const int gp = lane >> 2, qd = lane & 3;

    #pragma unroll
    for (int ni = 0; ni < 8; ni++) {
        const int n0 = n0b + Cn + ni * 8;
        const int h = n0 >> 6, d0 = (n0 & 63) + qd * 2;
        const float2 bb = *(const float2*)&bias[n0 + qd * 2];
        #pragma unroll
        for (int mi = 0; mi < 2; mi++) {
            const int s = mt * 128 + Rm + mi * 16 + gp;
            float* p0 = out + (((size_t)h * S_TOT + s) << 6) + d0;
            float* p1 = out + (((size_t)h * S_TOT + s + 8) << 6) + d0;
            *(float2*)p0 = make_float2(acc[mi][ni][0] + bb.x, acc[mi][ni][1] + bb.y);
            *(float2*)p1 = make_float2(acc[mi][ni][2] + bb.x, acc[mi][ni][3] + bb.y);
        }
    }
}

__global__ __launch_bounds__(256, 2)
void out_mma(const __nv_bfloat16* __restrict__ Ohi, const __nv_bfloat16* __restrict__ Olo,
             const __nv_bfloat16* __restrict__ Whi8, const __nv_bfloat16* __restrict__ Wlo8,
             const float* __restrict__ bo, const float* __restrict__ bao,
             float* __restrict__ out)
{
    extern __shared__ __align__(16) char smem[];
    const int nt = blockIdx.x, mt = blockIdx.y;
    const int r0 = mt * 128;
    const bool img = (r0 < S_IMG);
    const size_t arow = img ? (size_t)(S_TXT + r0) : (size_t)(r0 - S_IMG);
    const int widx = img ? 6 : 7;

    const __nv_bfloat16* Ah = Ohi + arow * DMODEL;
    const __nv_bfloat16* Al = Olo + arow * DMODEL;
    const __nv_bfloat16* Wh = Whi8 + (size_t)widx * WSZ + (size_t)nt * 128 * DMODEL;
    const __nv_bfloat16* Wl = Wlo8 + (size_t)widx * WSZ + (size_t)nt * 128 * DMODEL;
    const float* bias = img ? bo : bao;

    float acc[2][8][4];
    mma_core(Ah, Al, Wh, Wl, smem, acc);

    const int lane = threadIdx.x & 31, wid = threadIdx.x >> 5;
    const int Rm = (wid & 3) * 32, Cn = (wid >> 2) * 64;
    const int gp = lane >> 2, qd = lane & 3;

    #pragma unroll
    for (int ni = 0; ni < 8; ni++) {
        const int n0 = nt * 128 + Cn + ni * 8 + qd * 2;
        const float2 bb = *(const float2*)&bias[n0];
        #pragma unroll
        for (int mi = 0; mi < 2; mi++) {
            const int m = r0 + Rm + mi * 16 + gp;
            *(float2*)(out + (size_t)m * DMODEL + n0) =
                make_float2(acc[mi][ni][0] + bb.x, acc[mi][ni][1] + bb.y);
            *(float2*)(out + (size_t)(m + 8) * DMODEL + n0) =
                make_float2(acc[mi][ni][2] + bb.x, acc[mi][ni][3] + bb.y);
        }
    }
}

// ================= tensor-core flash attention (ldmatrix) =================
#define FSTRIDE 72
#define FTILE   (64 * FSTRIDE * 2)
#define FL_Q    0
#define FL_ST   (2 * FTILE)
#define FL_STG  (4 * FTILE)
#define FLASH2_SMEM (FL_ST + 2 * FL_STG)  // 92160

__global__ __launch_bounds__(256, 2)
void flash_mma(const __nv_bfloat16* __restrict__ Qh_g, const __nv_bfloat16* __restrict__ Ql_g,
               const __nv_bfloat16* __restrict__ Kh_g, const __nv_bfloat16* __restrict__ Kl_g,
               const __nv_bfloat16* __restrict__ Vth_g, const __nv_bfloat16* __restrict__ Vtl_g,
               __nv_bfloat16* __restrict__ Ohi, __nv_bfloat16* __restrict__ Olo)
{
    extern __shared__ __align__(16) char smem[];
    const int tid = threadIdx.x, lane = tid & 31, wid = tid >> 5;
    const int qw = wid & 3, kw = wid >> 2;
    const int gp = lane >> 2, qd = lane & 3;
    const int lr = lane & 7, sel = lane >> 3;
    const int aOff = ((sel & 1) * 8 + lr) * FSTRIDE + (sel & 2) * 4;
    const int bOff = ((sel >> 1) * 8 + lr) * FSTRIDE + (sel & 1) * 8;
    const int h = blockIdx.y, q0 = blockIdx.x * 64;
    const unsigned sb = smem_u32(smem);

    const size_t hb  = (size_t)h * S_TOT * DH;
    const size_t hbT = (size_t)h * DH * S_TOT;

    // stage Q once
    {
        const __nv_bfloat16* src[2] = {Qh_g + hb + (size_t)q0 * DH, Ql_g + hb + (size_t)q0 * DH};
        #pragma unroll
        for (int t = 0; t < 2; t++) {
            const unsigned db = sb + FL_Q + t * FTILE;
            for (int i = tid; i < 512; i += 256) {
                const int row = i >> 3, cg = i & 7;
                cp16(db + (row * FSTRIDE + cg * 8) * 2, src[t] + (size_t)row * DH + cg * 8);
            }
        }
        asm volatile("cp.async.commit_group;" ::: "memory");
    }

    auto issueKV = [&](int kt, int stage) {
        const __nv_bfloat16* src[4] = {
            Kh_g  + hb  + (size_t)(kt * 64) * DH,
            Kl_g  + hb  + (size_t)(kt * 64) * DH,
            Vth_g + hbT + kt * 64,
            Vtl_g + hbT + kt * 64};
        #pragma unroll
        for (int t = 0; t < 4; t++) {
            const unsigned db = sb + FL_ST + stage * FL_STG + t * FTILE;
            const size_t rs = (t < 2) ? (size_t)DH : (size_t)S_TOT;
            for (int i = tid; i < 512; i += 256) {
                const int row = i >> 3, cg = i & 7;
                cp16(db + (row * FSTRIDE + cg * 8) * 2, src[t] + (size_t)row * rs + cg * 8);
            }
        }
        asm volatile("cp.async.commit_group;" ::: "memory");
    };

    issueKV(0, 0);

    float oacc[8][4];
    #pragma unroll
    for (int ni = 0; ni < 8; ni++)
        #pragma unroll
        for (int j = 0; j < 4; j++) oacc[ni][j] = 0.0f;
    float lpart[2] = {0.0f, 0.0f};

    for (int kt = 0; kt < S_TOT / 64; kt++) {
        asm volatile("cp.async.wait_group 0;" ::: "memory");
        __syncthreads();
        if (kt + 1 < S_TOT / 64) issueKV(kt + 1, (kt + 1) & 1);

        const unsigned uK = sb + FL_ST + (kt & 1) * FL_STG;
        const unsigned uV = uK + 2 * FTILE;

        // ---- S = Q K^T (3-term) ----
        float sacc[4][4];
        #pragma unroll
        for (int ni = 0; ni < 4; ni++)
            #pragma unroll
            for (int j = 0; j < 4; j++) sacc[ni][j] = 0.0f;

        #pragma unroll
        for (int k0 = 0; k0 < 64; k0 += 16) {
            uint32_t ah[4], al[4];
            const unsigned ao = sb + FL_Q + 2u * (qw * 16 * FSTRIDE + k0 + aOff);
            ldsm4(ah, ao);
            ldsm4(al, ao + FTILE);
            #pragma unroll
            for (int np = 0; np < 2; np++) {
                uint32_t bh[4], bl[4];
                const unsigned bo = uK + 2u * ((kw * 32 + np * 16) * FSTRIDE + k0 + bOff);
                ldsm4(bh, bo);
                ldsm4(bl, bo + FTILE);
                mma16816(sacc[2 * np],     ah, bh[0], bh[1]);
                mma16816(sacc[2 * np],     ah, bl[0], bl[1]);
                mma16816(sacc[2 * np],     al, bh[0], bh[1]);
                mma16816(sacc[2 * np + 1], ah, bh[2], bh[3]);
                mma16816(sacc[2 * np + 1], ah, bl[2], bl[3]);
                mma16816(sacc[2 * np + 1], al, bh[2], bh[3]);
            }
        }

        // ---- exp (no max: |s|<=8), build P hi/lo A-fragments in registers ----
        uint32_t pA[2][4], plA[2][4];
        #pragma unroll
        for (int ni = 0; ni < 4; ni++) {
            const float p0 = __expf(sacc[ni][0]), p1 = __expf(sacc[ni][1]);
            const float p2 = __expf(sacc[ni][2]), p3 = __expf(sacc[ni][3]);
            lpart[0] += p0 + p1;
            lpart[1] += p2 + p3;
            const int kc = ni >> 1, half = (ni & 1) << 1;
            pA[kc][half]      = bfpair(p0, p1);
            pA[kc][half + 1]  = bfpair(p2, p3);
            plA[kc][half]     = bfpair(p0 - bfround(p0), p1 - bfround(p1));
            plA[kc][half + 1] = bfpair(p2 - bfround(p2), p3 - bfround(p3));
        }

        // ---- O += P V (3-term), B = Vt[d][kpos] ----
        #pragma unroll
        for (int kc = 0; kc < 2; kc++) {
            const int kk = kw * 32 + kc * 16;
            #pragma unroll
            for (int np = 0; np < 4; np++) {
                uint32_t bh[4], bl[4];
                const unsigned bo = uV + 2u * (np * 16 * FSTRIDE + kk + bOff);
                ldsm4(bh, bo);
                ldsm4(bl, bo + FTILE);
                mma16816(oacc[2 * np],     pA[kc],  bh[0], bh[1]);
                mma16816(oacc[2 * np],     pA[kc],  bl[0], bl[1]);
                mma16816(oacc[2 * np],     plA[kc], bh[0], bh[1]);
                mma16816(oacc[2 * np + 1], pA[kc],  bh[2], bh[3]);
                mma16816(oacc[2 * np + 1], pA[kc],  bl[2], bl[3]);
                mma16816(oacc[2 * np + 1], plA[kc], bh[2], bh[3]);
            }
        }
    }

    // ---- final reduction across k-warps + 1/l scaling, bf16 hi/lo output ----
    __syncthreads();
    float* ored = (float*)(smem + FL_ST);
    float* lred = (float*)(smem + FL_ST + 4 * 16 * 68 * 4);

    #pragma unroll
    for (int off = 1; off < 4; off <<= 1) {
        lpart[0] += __shfl_xor_sync(0xffffffffu, lpart[0], off);
        lpart[1] += __shfl_xor_sync(0xffffffffu, lpart[1], off);
    }
    if (qd == 0) {
        lred[(kw * 4 + qw) * 16 + gp]     = lpart[0];
        lred[(kw * 4 + qw) * 16 + gp + 8] = lpart[1];
    }
    if (kw == 1) {
        #pragma unroll
        for (int ni = 0; ni < 8; ni++) {
            *(float2*)&ored[(qw * 16 + gp) * 68 + ni * 8 + 2 * qd] =
                make_float2(oacc[ni][0], oacc[ni][1]);
            *(float2*)&ored[(qw * 16 + gp + 8) * 68 + ni * 8 + 2 * qd] =
                make_float2(oacc[ni][2], oacc[ni][3]);
        }
    }
    __syncthreads();
    if (kw == 0) {
        const float inv0 = 1.0f / (lred[qw * 16 + gp]     + lred[(4 + qw) * 16 + gp]);
        const float inv1 = 1.0f / (lred[qw * 16 + gp + 8] + lred[(4 + qw) * 16 + gp + 8]);
        #pragma unroll
        for (int ni = 0; ni < 8; ni++) {
            const float2 a = *(const float2*)&ored[(qw * 16 + gp) * 68 + ni * 8 + 2 * qd];
            const float2 b = *(const float2*)&ored[(qw * 16 + gp + 8) * 68 + ni * 8 + 2 * qd];
            const int col = h * 64 + ni * 8 + 2 * qd;
            const float v0 = (oacc[ni][0] + a.x) * inv0, v1 = (oacc[ni][1] + a.y) * inv0;
            const float v2 = (oacc[ni][2] + b.x) * inv1, v3 = (oacc[ni][3] + b.y) * inv1;
            const size_t o0 = (size_t)(q0 + qw * 16 + gp) * DMODEL + col;
            const size_t o1 = (size_t)(q0 + qw * 16 + gp + 8) * DMODEL + col;
            const __nv_bfloat16 h0 = __float2bfloat16(v0), h1 = __float2bfloat16(v1);
            const __nv_bfloat16 h2 = __float2bfloat16(v2), h3 = __float2bfloat16(v3);
            *(__nv_bfloat162*)&Ohi[o0] = __nv_bfloat162{h0, h1};
            *(__nv_bfloat162*)&Ohi[o1] = __nv_bfloat162{h2, h3};
            *(__nv_bfloat162*)&Olo[o0] = __nv_bfloat162{
                __float2bfloat16(v0 - __bfloat162float(h0)),
                __float2bfloat16(v1 - __bfloat162float(h1))};
            *(__nv_bfloat162*)&Olo[o1] = __nv_bfloat162{
                __float2bfloat16(v2 - __bfloat162float(h2)),
                __float2bfloat16(v3 - __bfloat162float(h3))};
        }
    }
}

// ---------------- launch ----------------
extern "C" void kernel_launch(void* const* d_in, const int* in_sizes, int n_in,
                              void* d_out, int out_size)
{
    const float* hid  = (const float*)d_in[0];
    const float* enc  = (const float*)d_in[1];
    const float* rcos = (const float*)d_in[2];
    const float* rsin = (const float*)d_in[3];
    const float* Wq  = (const float*)d_in[4];  const float* bq  = (const float*)d_in[5];
    const float* Wk  = (const float*)d_in[6];  const float* bk  = (const float*)d_in[7];
    const float* Wv  = (const float*)d_in[8];  const float* bv  = (const float*)d_in[9];
    const float* Waq = (const float*)d_in[10]; const float* baq = (const float*)d_in[11];
    const float* Wak = (const float*)d_in[12]; const float* bak = (const float*)d_in[13];
    const float* Wav = (const float*)d_in[14]; const float* bav = (const float*)d_in[15];
    const float* Wo  = (const float*)d_in[16]; const float* bo  = (const float*)d_in[17];
    const float* Wao = (const float*)d_in[18]; const float* bao = (const float*)d_in[19];
    const float* gq  = (const float*)d_in[20]; const float* gk  = (const float*)d_in[21];
    const float* gaq = (const float*)d_in[22]; const float* gak = (const float*)d_in[23];
    float* out = (float*)d_out;

    float *Qp, *Kp, *Vp;
    cudaGetSymbolAddress((void**)&Qp, g_Q);
    cudaGetSymbolAddress((void**)&Kp, g_K);
    cudaGetSymbolAddress((void**)&Vp, g_V);
    __nv_bfloat16 *WhiP, *WloP, *XhiP, *XloP, *OhiP, *OloP;
    __nv_bfloat16 *QhP, *QlP, *KhP, *KlP, *VthP, *VtlP;
    cudaGetSymbolAddress((void**)&WhiP, g_Whi);
    cudaGetSymbolAddress((void**)&WloP, g_Wlo);
    cudaGetSymbolAddress((void**)&XhiP, g_Xhi);
    cudaGetSymbolAddress((void**)&XloP, g_Xlo);
    cudaGetSymbolAddress((void**)&OhiP, g_Ohi);
    cudaGetSymbolAddress((void**)&OloP, g_Olo);
    cudaGetSymbolAddress((void**)&QhP, g_Qhi);
    cudaGetSymbolAddress((void**)&QlP, g_Qlo);
    cudaGetSymbolAddress((void**)&KhP, g_Khi);
    cudaGetSymbolAddress((void**)&KlP, g_Klo);
    cudaGetSymbolAddress((void**)&VthP, g_Vthi);
    cudaGetSymbolAddress((void**)&VtlP, g_Vtlo);

    // splits: weights (one launch) + activations
    splitW<<<dim3((WSZ / 4 + 255) / 256, 8), 256>>>(Wq, Wk, Wv, Waq, Wak, Wav, Wo, Wao, WhiP, WloP);
    split4<<<(S_TXT * DMODEL / 4 + 255) / 256, 256>>>(enc, XhiP, XloP, S_TXT * DMODEL / 4);
    split4<<<(S_IMG * DMODEL / 4 + 255) / 256, 256>>>(hid, XhiP + (size_t)S_TXT * DMODEL,
                                                      XloP + (size_t)S_TXT * DMODEL, S_IMG * DMODEL / 4);

    // QKV projections (tensor cores) -> fp32 [h][s][d]
    cudaFuncSetAttribute(qkv_mma, cudaFuncAttributeMaxDynamicSharedMemorySize, GEMM_SMEM);
    qkv_mma<<<dim3(36, 20), 256, GEMM_SMEM>>>(XhiP, XloP, WhiP, WloP,
                                              bq, bk, bv, baq, bak, bav, Qp, Kp, Vp);

    // RMS norm + gain + RoPE, fused bf16 hi/lo split (Q scaled by 0.125)
    rmsrope_split<<<NH * S_TOT / 4, 128>>>(Qp, gaq, gq, rcos, rsin, 0.125f, QhP, QlP);
    rmsrope_split<<<NH * S_TOT / 4, 128>>>(Kp, gak, gk, rcos, rsin, 1.0f,   KhP, KlP);

    // V transpose+split
    vtsplit<<<dim3(S_TOT / 32, DH / 32, NH), dim3(32, 8)>>>(Vp, VthP, VtlP);

    // tensor-core flash attention -> bf16 hi/lo O[s][h*64+d]
    cudaFuncSetAttribute(flash_mma, cudaFuncAttributeMaxDynamicSharedMemorySize, FLASH2_SMEM);
    flash_mma<<<dim3(S_TOT / 64, NH), 256, FLASH2_SMEM>>>(QhP, QlP, KhP, KlP, VthP, VtlP, OhiP, OloP);

    // output projections (tensor cores)
    cudaFuncSetAttribute(out_mma, cudaFuncAttributeMaxDynamicSharedMemorySize, GEMM_SMEM);
    out_mma<<<dim3(12, 20), 256, GEMM_SMEM>>>(OhiP, OloP, WhiP, WloP, bo, bao, out);
}